// round 1
// baseline (speedup 1.0000x reference)
#include <cuda_runtime.h>
#include <cstdint>

#define B_   256
#define T_   512
#define IN_  64
#define H_   128
#define G_   512   // 4*H

// 256 MB scratch for precomputed layer-0 input projections, layout [t][b][g]
__device__ float g_xg0[(size_t)T_ * B_ * G_];

// ---------------------------------------------------------------------------
// helpers
// ---------------------------------------------------------------------------
__device__ __forceinline__ uint32_t smem_u32(const void* p) {
    uint32_t a;
    asm("{ .reg .u64 t; cvta.to.shared.u64 t, %1; cvt.u32.u64 %0, t; }"
        : "=r"(a) : "l"(p));
    return a;
}
__device__ __forceinline__ uint32_t mapa_u32(uint32_t addr, uint32_t rank) {
    uint32_t r;
    asm("mapa.shared::cluster.u32 %0, %1, %2;" : "=r"(r) : "r"(addr), "r"(rank));
    return r;
}
__device__ __forceinline__ void stc_f32(uint32_t addr, float v) {
    asm volatile("st.shared::cluster.f32 [%0], %1;" :: "r"(addr), "f"(v));
}
#define CLUSTER_SYNC() do { \
    asm volatile("barrier.cluster.arrive.aligned;" ::: "memory"); \
    asm volatile("barrier.cluster.wait.aligned;"   ::: "memory"); \
} while (0)

__device__ __forceinline__ float sigf(float x)  { return 1.0f / (1.0f + __expf(-x)); }
__device__ __forceinline__ float tanh_f(float x){ return 1.0f - 2.0f / (__expf(2.0f * x) + 1.0f); }

// ---------------------------------------------------------------------------
// Phase 1: xg0[t][b][g] = (b_ih0+b_hh0)[g] + sum_i x[b][t][i] * w_ih0[g][i]
// row index n = b*T + t (x is [B,T,IN] contiguous). Block: 64 rows x 512 cols.
// ---------------------------------------------------------------------------
#define P1_ROWS    64
#define P1_THREADS 256
#define P1_XT_STRIDE 68
// smem floats: WT [64][512] + xT [64][68] + bias [512]
#define P1_WT_OFF   0
#define P1_XT_OFF   (64*512)
#define P1_B_OFF    (P1_XT_OFF + 64*P1_XT_STRIDE)
#define P1_SMEM_FLOATS (P1_B_OFF + 512)

__global__ void __launch_bounds__(P1_THREADS)
p1_kernel(const float* __restrict__ x,
          const float* __restrict__ w_ih0,
          const float* __restrict__ b_ih0,
          const float* __restrict__ b_hh0)
{
    extern __shared__ float s1[];
    float* WT   = s1 + P1_WT_OFF;   // [k][g], stride 512
    float* xT   = s1 + P1_XT_OFF;   // [k][row], stride 68
    float* bias = s1 + P1_B_OFF;

    const int tid     = threadIdx.x;
    const int rowbase = blockIdx.x * P1_ROWS;

    // load W transposed: WT[k][g] = w_ih0[g*64+k]
    for (int idx = tid; idx < G_ * IN_; idx += P1_THREADS) {
        int g = idx >> 6, k = idx & 63;
        WT[k * 512 + g] = w_ih0[idx];
    }
    for (int g = tid; g < G_; g += P1_THREADS)
        bias[g] = b_ih0[g] + b_hh0[g];
    // load x tile transposed (64 rows x 64 contiguous floats)
    for (int idx = tid; idx < P1_ROWS * IN_ / 4; idx += P1_THREADS) {
        int row = idx >> 4, kq = idx & 15;
        float4 v = reinterpret_cast<const float4*>(x + (size_t)(rowbase + row) * IN_)[kq];
        int k = kq * 4;
        xT[(k + 0) * P1_XT_STRIDE + row] = v.x;
        xT[(k + 1) * P1_XT_STRIDE + row] = v.y;
        xT[(k + 2) * P1_XT_STRIDE + row] = v.z;
        xT[(k + 3) * P1_XT_STRIDE + row] = v.w;
    }
    __syncthreads();

    const int cg  = tid & 63;   // 0..63 col group
    const int rgq = tid >> 6;   // 0..3

    for (int it = 0; it < 4; ++it) {
        const int rg = it * 4 + rgq;   // row group, rows rg*4..rg*4+3
        float a[4][8];
        #pragma unroll
        for (int r = 0; r < 4; ++r)
            #pragma unroll
            for (int c = 0; c < 8; ++c) a[r][c] = 0.0f;

        #pragma unroll 4
        for (int k = 0; k < IN_; ++k) {
            float4 xv = *reinterpret_cast<const float4*>(xT + k * P1_XT_STRIDE + (rg << 2));
            float4 w0 = *reinterpret_cast<const float4*>(WT + (k << 9) + (cg << 2));
            float4 w1 = *reinterpret_cast<const float4*>(WT + (k << 9) + 256 + (cg << 2));
            float xr[4] = {xv.x, xv.y, xv.z, xv.w};
            #pragma unroll
            for (int r = 0; r < 4; ++r) {
                a[r][0] += xr[r] * w0.x; a[r][1] += xr[r] * w0.y;
                a[r][2] += xr[r] * w0.z; a[r][3] += xr[r] * w0.w;
                a[r][4] += xr[r] * w1.x; a[r][5] += xr[r] * w1.y;
                a[r][6] += xr[r] * w1.z; a[r][7] += xr[r] * w1.w;
            }
        }
        float4 bb0 = *reinterpret_cast<const float4*>(bias + (cg << 2));
        float4 bb1 = *reinterpret_cast<const float4*>(bias + 256 + (cg << 2));
        #pragma unroll
        for (int r = 0; r < 4; ++r) {
            int n = rowbase + rg * 4 + r;
            int b = n >> 9;          // T = 512
            int t = n & 511;
            float* op = g_xg0 + ((size_t)t * B_ + b) * G_;
            float4 o0 = make_float4(a[r][0] + bb0.x, a[r][1] + bb0.y,
                                    a[r][2] + bb0.z, a[r][3] + bb0.w);
            float4 o1 = make_float4(a[r][4] + bb1.x, a[r][5] + bb1.y,
                                    a[r][6] + bb1.z, a[r][7] + bb1.w);
            *reinterpret_cast<float4*>(op + (cg << 2))        = o0;
            *reinterpret_cast<float4*>(op + 256 + (cg << 2))  = o1;
        }
    }
}

// ---------------------------------------------------------------------------
// Phase 2: persistent fused 2-layer scan.
// 32 clusters x 4 CTAs, 8 batches per cluster. CTA rank r owns hidden cols
// [r*32, r*32+32) of both layers (gate rows q*128 + r*32 + j, q=0..3).
// smem weights stored K-major with stride 136 floats (bank-conflict-free with
// kc-interleaved K split). h state double-buffered: H[2][256][8] (k-major),
// rows 0..127 = h0, 128..255 = h1.
// ---------------------------------------------------------------------------
#define SC_THREADS 256
#define CL_N 4
#define BPC  8
#define WSTRIDE 136
#define W0T_OFF 0
#define W1T_OFF (128*WSTRIDE)                 // 17408
#define H_OFF   (W1T_OFF + 256*WSTRIDE)       // 52224
#define GT_OFF  (H_OFF + 2*256*8)             // 56320
#define B1_OFF  (GT_OFF + 8*128)              // 57344
#define SC_SMEM_FLOATS (B1_OFF + 128)         // 57472 -> 229888 B

__global__ void __launch_bounds__(SC_THREADS, 1) __cluster_dims__(CL_N, 1, 1)
scan_kernel(const float* __restrict__ w_hh0,
            const float* __restrict__ w_ih1,
            const float* __restrict__ w_hh1,
            const float* __restrict__ b_ih1,
            const float* __restrict__ b_hh1,
            const float* __restrict__ fc_w,
            const float* __restrict__ fc_b,
            float* __restrict__ out)
{
    extern __shared__ float s2[];
    float* W0T   = s2 + W0T_OFF;   // [k 0..127][rl 0..127], stride 136
    float* W1T   = s2 + W1T_OFF;   // [k 0..255][rl], rows 0..127 = w_ih1, 128..255 = w_hh1
    float* Hbuf  = s2 + H_OFF;     // [buf][k][b] : buf*2048 + k*8 + b
    float* gates = s2 + GT_OFF;    // [b][rl] : b*128 + rl
    float* bias1 = s2 + B1_OFF;    // [rl]

    const int tid = threadIdx.x;
    uint32_t rank;
    asm("mov.u32 %0, %%cluster_ctarank;" : "=r"(rank));
    const int irank = (int)rank;
    const int cbase = (blockIdx.x >> 2) * BPC;

    // ---- prologue: load own weight slices, transposed ----
    for (int idx = tid; idx < 128 * 128; idx += SC_THREADS) {
        int rl = idx >> 7, k = idx & 127;
        int grow = ((rl >> 5) << 7) + irank * 32 + (rl & 31);
        W0T[k * WSTRIDE + rl]         = w_hh0[grow * H_ + k];
        W1T[k * WSTRIDE + rl]         = w_ih1[grow * H_ + k];
        W1T[(128 + k) * WSTRIDE + rl] = w_hh1[grow * H_ + k];
    }
    for (int rl = tid; rl < 128; rl += SC_THREADS) {
        int grow = ((rl >> 5) << 7) + irank * 32 + (rl & 31);
        bias1[rl] = b_ih1[grow] + b_hh1[grow];
    }
    for (int i = tid; i < 2 * 256 * 8; i += SC_THREADS) Hbuf[i] = 0.0f;

    // remote smem base addresses of Hbuf for all 4 ranks
    uint32_t hloc = smem_u32(Hbuf);
    uint32_t hrem[4];
    #pragma unroll
    for (int r = 0; r < 4; ++r) hrem[r] = mapa_u32(hloc, (uint32_t)r);

    CLUSTER_SYNC();

    // GEMM thread mapping: 256 threads = 64 tiles x 4 k-chunks
    const int kc = tid & 3;          // k-chunk (interleaved: k = 4*ii + kc)
    const int tl = tid >> 2;
    const int rg = tl & 31;          // rows rg*4 .. rg*4+3 (of 128 local gate rows)
    const int bg = tl >> 5;          // batches bg*4 .. bg*4+3 (of 8)
    // elementwise mapping: thread <-> (batch eb, own col ej)
    const int eb = tid >> 5;         // 0..7
    const int ej = tid & 31;         // 0..31
    const float* xgbase = g_xg0 + (size_t)(cbase + eb) * G_ + irank * 32 + ej;

    float c0 = 0.0f, c1 = 0.0f;

    for (int t = 0; t < T_; ++t) {
        const int p = t & 1;
        // prefetch xg for this (b, col): gates i,f,g,o at +0,+128,+256,+384
        const float* xgp = xgbase + (size_t)t * (B_ * G_);
        float xg_i = __ldg(xgp);
        float xg_f = __ldg(xgp + 128);
        float xg_g = __ldg(xgp + 256);
        float xg_o = __ldg(xgp + 384);

        // ---- GEMM0: gates0 = W0 @ h0_prev ----
        {
            const float* hb = Hbuf + (p << 11);   // H[p][0..127][.]
            float a[4][4];
            #pragma unroll
            for (int r = 0; r < 4; ++r)
                #pragma unroll
                for (int b = 0; b < 4; ++b) a[r][b] = 0.0f;
            #pragma unroll 8
            for (int ii = 0; ii < 32; ++ii) {
                int k = (ii << 2) + kc;
                float4 w = *reinterpret_cast<const float4*>(W0T + k * WSTRIDE + (rg << 2));
                float4 h = *reinterpret_cast<const float4*>(hb + (k << 3) + (bg << 2));
                a[0][0] += w.x*h.x; a[0][1] += w.x*h.y; a[0][2] += w.x*h.z; a[0][3] += w.x*h.w;
                a[1][0] += w.y*h.x; a[1][1] += w.y*h.y; a[1][2] += w.y*h.z; a[1][3] += w.y*h.w;
                a[2][0] += w.z*h.x; a[2][1] += w.z*h.y; a[2][2] += w.z*h.z; a[2][3] += w.z*h.w;
                a[3][0] += w.w*h.x; a[3][1] += w.w*h.y; a[3][2] += w.w*h.z; a[3][3] += w.w*h.w;
            }
            #pragma unroll
            for (int r = 0; r < 4; ++r)
                #pragma unroll
                for (int b = 0; b < 4; ++b) {
                    float v = a[r][b];
                    v += __shfl_xor_sync(0xffffffffu, v, 1);
                    v += __shfl_xor_sync(0xffffffffu, v, 2);
                    a[r][b] = v;
                }
            if (kc == 0) {
                #pragma unroll
                for (int r = 0; r < 4; ++r)
                    #pragma unroll
                    for (int b = 0; b < 4; ++b)
                        gates[(((bg << 2) + b) << 7) + (rg << 2) + r] = a[r][b];
            }
        }
        __syncthreads();

        // ---- elementwise layer 0 -> h0_new, broadcast to cluster ----
        {
            float gi = gates[(eb << 7) + ej]      + xg_i;
            float gf = gates[(eb << 7) + 32 + ej] + xg_f;
            float gg = gates[(eb << 7) + 64 + ej] + xg_g;
            float go = gates[(eb << 7) + 96 + ej] + xg_o;
            float iv = sigf(gi), fv = sigf(gf), gv = tanh_f(gg), ov = sigf(go);
            c0 = fv * c0 + iv * gv;
            float h0 = ov * tanh_f(c0);
            uint32_t off = (uint32_t)((((1 - p) << 11) + ((irank * 32 + ej) << 3) + eb) << 2);
            #pragma unroll
            for (int r = 0; r < 4; ++r) stc_f32(hrem[r] + off, h0);
        }
        CLUSTER_SYNC();

        // ---- GEMM1: gates1 = W_ih1 @ h0_new + W_hh1 @ h1_prev (K=256) ----
        {
            const float* hbA = Hbuf + ((1 - p) << 11);  // h0_new at rows 0..127
            const float* hbB = Hbuf + (p << 11);        // h1_prev at rows 128..255
            float a[4][4];
            #pragma unroll
            for (int r = 0; r < 4; ++r)
                #pragma unroll
                for (int b = 0; b < 4; ++b) a[r][b] = 0.0f;
            #pragma unroll 8
            for (int ii = 0; ii < 32; ++ii) {
                int k = (ii << 2) + kc;
                float4 w = *reinterpret_cast<const float4*>(W1T + k * WSTRIDE + (rg << 2));
                float4 h = *reinterpret_cast<const float4*>(hbA + (k << 3) + (bg << 2));
                a[0][0] += w.x*h.x; a[0][1] += w.x*h.y; a[0][2] += w.x*h.z; a[0][3] += w.x*h.w;
                a[1][0] += w.y*h.x; a[1][1] += w.y*h.y; a[1][2] += w.y*h.z; a[1][3] += w.y*h.w;
                a[2][0] += w.z*h.x; a[2][1] += w.z*h.y; a[2][2] += w.z*h.z; a[2][3] += w.z*h.w;
                a[3][0] += w.w*h.x; a[3][1] += w.w*h.y; a[3][2] += w.w*h.z; a[3][3] += w.w*h.w;
            }
            #pragma unroll 8
            for (int ii = 32; ii < 64; ++ii) {
                int k = (ii << 2) + kc;                 // 128..255
                float4 w = *reinterpret_cast<const float4*>(W1T + k * WSTRIDE + (rg << 2));
                float4 h = *reinterpret_cast<const float4*>(hbB + (k << 3) + (bg << 2));
                a[0][0] += w.x*h.x; a[0][1] += w.x*h.y; a[0][2] += w.x*h.z; a[0][3] += w.x*h.w;
                a[1][0] += w.y*h.x; a[1][1] += w.y*h.y; a[1][2] += w.y*h.z; a[1][3] += w.y*h.w;
                a[2][0] += w.z*h.x; a[2][1] += w.z*h.y; a[2][2] += w.z*h.z; a[2][3] += w.z*h.w;
                a[3][0] += w.w*h.x; a[3][1] += w.w*h.y; a[3][2] += w.w*h.z; a[3][3] += w.w*h.w;
            }
            #pragma unroll
            for (int r = 0; r < 4; ++r)
                #pragma unroll
                for (int b = 0; b < 4; ++b) {
                    float v = a[r][b];
                    v += __shfl_xor_sync(0xffffffffu, v, 1);
                    v += __shfl_xor_sync(0xffffffffu, v, 2);
                    a[r][b] = v;
                }
            if (kc == 0) {
                #pragma unroll
                for (int r = 0; r < 4; ++r)
                    #pragma unroll
                    for (int b = 0; b < 4; ++b)
                        gates[(((bg << 2) + b) << 7) + (rg << 2) + r] = a[r][b];
            }
        }
        __syncthreads();

        // ---- elementwise layer 1 -> h1_new, broadcast to cluster ----
        {
            float gi = gates[(eb << 7) + ej]      + bias1[ej];
            float gf = gates[(eb << 7) + 32 + ej] + bias1[32 + ej];
            float gg = gates[(eb << 7) + 64 + ej] + bias1[64 + ej];
            float go = gates[(eb << 7) + 96 + ej] + bias1[96 + ej];
            float iv = sigf(gi), fv = sigf(gf), gv = tanh_f(gg), ov = sigf(go);
            c1 = fv * c1 + iv * gv;
            float h1 = ov * tanh_f(c1);
            uint32_t off = (uint32_t)((((1 - p) << 11) + ((128 + irank * 32 + ej) << 3) + eb) << 2);
            #pragma unroll
            for (int r = 0; r < 4; ++r) stc_f32(hrem[r] + off, h1);
        }
        CLUSTER_SYNC();
    }

    // ---- epilogue: out[b] = fc_b + sum_c h1_last[b][c] * fc_w[c] ----
    // t=511 had p=1, so final h1 lives in buffer 0, rows 128..255.
    if (rank == 0) {
        const int b = tid >> 5;
        const int l = tid & 31;
        const float* h1p = Hbuf;   // buffer 0
        float ssum = 0.0f;
        #pragma unroll
        for (int cc = 0; cc < 4; ++cc) {
            int c = l * 4 + cc;
            ssum += h1p[((128 + c) << 3) + b] * __ldg(fc_w + c);
        }
        #pragma unroll
        for (int d = 16; d > 0; d >>= 1)
            ssum += __shfl_xor_sync(0xffffffffu, ssum, d);
        if (l == 0) out[cbase + b] = ssum + __ldg(fc_b);
    }
    CLUSTER_SYNC();
}

// ---------------------------------------------------------------------------
extern "C" void kernel_launch(void* const* d_in, const int* in_sizes, int n_in,
                              void* d_out, int out_size)
{
    const float* x     = (const float*)d_in[0];
    const float* w_ih0 = (const float*)d_in[1];
    const float* w_hh0 = (const float*)d_in[2];
    const float* b_ih0 = (const float*)d_in[3];
    const float* b_hh0 = (const float*)d_in[4];
    const float* w_ih1 = (const float*)d_in[5];
    const float* w_hh1 = (const float*)d_in[6];
    const float* b_ih1 = (const float*)d_in[7];
    const float* b_hh1 = (const float*)d_in[8];
    const float* fc_w  = (const float*)d_in[9];
    const float* fc_b  = (const float*)d_in[10];
    float* out = (float*)d_out;

    const int p1_smem = P1_SMEM_FLOATS * 4;
    const int sc_smem = SC_SMEM_FLOATS * 4;
    cudaFuncSetAttribute(p1_kernel,  cudaFuncAttributeMaxDynamicSharedMemorySize, p1_smem);
    cudaFuncSetAttribute(scan_kernel, cudaFuncAttributeMaxDynamicSharedMemorySize, sc_smem);

    // Phase 1: input projections for layer 0 (parallel over all timesteps)
    p1_kernel<<<(B_ * T_) / P1_ROWS, P1_THREADS, p1_smem>>>(x, w_ih0, b_ih0, b_hh0);
    // Phase 2: fused 2-layer sequential scan + FC head
    scan_kernel<<<(B_ / BPC) * CL_N, SC_THREADS, sc_smem>>>(
        w_hh0, w_ih1, w_hh1, b_ih1, b_hh1, fc_w, fc_b, out);
}

// round 2
// speedup vs baseline: 1.0171x; 1.0171x over previous
#include <cuda_runtime.h>
#include <cstdint>

#define B_   256
#define T_   512
#define IN_  64
#define H_   128
#define G_   512   // 4*H

// 256 MB scratch for precomputed layer-0 input projections, layout [t][b][g]
__device__ float g_xg0[(size_t)T_ * B_ * G_];

// ---------------------------------------------------------------------------
// helpers
// ---------------------------------------------------------------------------
__device__ __forceinline__ uint32_t smem_u32(const void* p) {
    uint32_t a;
    asm("{ .reg .u64 t; cvta.to.shared.u64 t, %1; cvt.u32.u64 %0, t; }"
        : "=r"(a) : "l"(p));
    return a;
}
__device__ __forceinline__ uint32_t mapa_u32(uint32_t addr, uint32_t rank) {
    uint32_t r;
    asm("mapa.shared::cluster.u32 %0, %1, %2;" : "=r"(r) : "r"(addr), "r"(rank));
    return r;
}
__device__ __forceinline__ void stc_f32(uint32_t addr, float v) {
    asm volatile("st.shared::cluster.f32 [%0], %1;" :: "r"(addr), "f"(v));
}
#define CLUSTER_SYNC() do { \
    asm volatile("barrier.cluster.arrive.aligned;" ::: "memory"); \
    asm volatile("barrier.cluster.wait.aligned;"   ::: "memory"); \
} while (0)

__device__ __forceinline__ float sigf(float x)  { return 1.0f / (1.0f + __expf(-x)); }
__device__ __forceinline__ float tanh_f(float x){ return 1.0f - 2.0f / (__expf(2.0f * x) + 1.0f); }

// ---------------------------------------------------------------------------
// Phase 1: xg0[t][b][g] = (b_ih0+b_hh0)[g] + sum_i x[b][t][i] * w_ih0[g][i]
// row index n = b*T + t (x is [B,T,IN] contiguous). Block: 64 rows x 512 cols.
// ---------------------------------------------------------------------------
#define P1_ROWS    64
#define P1_THREADS 256
#define P1_XT_STRIDE 68
// smem floats: WT [64][512] + xT [64][68] + bias [512]
#define P1_WT_OFF   0
#define P1_XT_OFF   (64*512)
#define P1_B_OFF    (P1_XT_OFF + 64*P1_XT_STRIDE)
#define P1_SMEM_FLOATS (P1_B_OFF + 512)

__global__ void __launch_bounds__(P1_THREADS)
p1_kernel(const float* __restrict__ x,
          const float* __restrict__ w_ih0,
          const float* __restrict__ b_ih0,
          const float* __restrict__ b_hh0)
{
    extern __shared__ float s1[];
    float* WT   = s1 + P1_WT_OFF;   // [k][g], stride 512
    float* xT   = s1 + P1_XT_OFF;   // [k][row], stride 68
    float* bias = s1 + P1_B_OFF;

    const int tid     = threadIdx.x;
    const int rowbase = blockIdx.x * P1_ROWS;

    // load W transposed: WT[k][g] = w_ih0[g*64+k]
    for (int idx = tid; idx < G_ * IN_; idx += P1_THREADS) {
        int g = idx >> 6, k = idx & 63;
        WT[k * 512 + g] = w_ih0[idx];
    }
    for (int g = tid; g < G_; g += P1_THREADS)
        bias[g] = b_ih0[g] + b_hh0[g];
    // load x tile transposed (64 rows x 64 contiguous floats)
    for (int idx = tid; idx < P1_ROWS * IN_ / 4; idx += P1_THREADS) {
        int row = idx >> 4, kq = idx & 15;
        float4 v = reinterpret_cast<const float4*>(x + (size_t)(rowbase + row) * IN_)[kq];
        int k = kq * 4;
        xT[(k + 0) * P1_XT_STRIDE + row] = v.x;
        xT[(k + 1) * P1_XT_STRIDE + row] = v.y;
        xT[(k + 2) * P1_XT_STRIDE + row] = v.z;
        xT[(k + 3) * P1_XT_STRIDE + row] = v.w;
    }
    __syncthreads();

    const int cg  = tid & 63;   // 0..63 col group
    const int rgq = tid >> 6;   // 0..3

    for (int it = 0; it < 4; ++it) {
        const int rg = it * 4 + rgq;   // row group, rows rg*4..rg*4+3
        float a[4][8];
        #pragma unroll
        for (int r = 0; r < 4; ++r)
            #pragma unroll
            for (int c = 0; c < 8; ++c) a[r][c] = 0.0f;

        #pragma unroll 4
        for (int k = 0; k < IN_; ++k) {
            float4 xv = *reinterpret_cast<const float4*>(xT + k * P1_XT_STRIDE + (rg << 2));
            float4 w0 = *reinterpret_cast<const float4*>(WT + (k << 9) + (cg << 2));
            float4 w1 = *reinterpret_cast<const float4*>(WT + (k << 9) + 256 + (cg << 2));
            float xr[4] = {xv.x, xv.y, xv.z, xv.w};
            #pragma unroll
            for (int r = 0; r < 4; ++r) {
                a[r][0] += xr[r] * w0.x; a[r][1] += xr[r] * w0.y;
                a[r][2] += xr[r] * w0.z; a[r][3] += xr[r] * w0.w;
                a[r][4] += xr[r] * w1.x; a[r][5] += xr[r] * w1.y;
                a[r][6] += xr[r] * w1.z; a[r][7] += xr[r] * w1.w;
            }
        }
        float4 bb0 = *reinterpret_cast<const float4*>(bias + (cg << 2));
        float4 bb1 = *reinterpret_cast<const float4*>(bias + 256 + (cg << 2));
        #pragma unroll
        for (int r = 0; r < 4; ++r) {
            int n = rowbase + rg * 4 + r;
            int b = n >> 9;          // T = 512
            int t = n & 511;
            float* op = g_xg0 + ((size_t)t * B_ + b) * G_;
            float4 o0 = make_float4(a[r][0] + bb0.x, a[r][1] + bb0.y,
                                    a[r][2] + bb0.z, a[r][3] + bb0.w);
            float4 o1 = make_float4(a[r][4] + bb1.x, a[r][5] + bb1.y,
                                    a[r][6] + bb1.z, a[r][7] + bb1.w);
            *reinterpret_cast<float4*>(op + (cg << 2))        = o0;
            *reinterpret_cast<float4*>(op + 256 + (cg << 2))  = o1;
        }
    }
}

// ---------------------------------------------------------------------------
// Phase 2: persistent fused 2-layer scan.
// 32 clusters x 4 CTAs, 8 batches per cluster. CTA rank r owns hidden cols
// [r*32, r*32+32) of both layers (gate rows q*128 + r*32 + j, q=0..3).
// smem weights stored K-major with stride 136 floats (bank-conflict-free with
// kc-interleaved K split). h state double-buffered: H[2][256][8] (k-major),
// rows 0..127 = h0, 128..255 = h1.
// ---------------------------------------------------------------------------
#define SC_THREADS 256
#define CL_N 4
#define BPC  8
#define WSTRIDE 136
#define W0T_OFF 0
#define W1T_OFF (128*WSTRIDE)                 // 17408
#define H_OFF   (W1T_OFF + 256*WSTRIDE)       // 52224
#define GT_OFF  (H_OFF + 2*256*8)             // 56320
#define B1_OFF  (GT_OFF + 8*128)              // 57344
#define SC_SMEM_FLOATS (B1_OFF + 128)         // 57472 -> 229888 B

__global__ void __launch_bounds__(SC_THREADS, 1) __cluster_dims__(CL_N, 1, 1)
scan_kernel(const float* __restrict__ w_hh0,
            const float* __restrict__ w_ih1,
            const float* __restrict__ w_hh1,
            const float* __restrict__ b_ih1,
            const float* __restrict__ b_hh1,
            const float* __restrict__ fc_w,
            const float* __restrict__ fc_b,
            float* __restrict__ out)
{
    extern __shared__ float s2[];
    float* W0T   = s2 + W0T_OFF;   // [k 0..127][rl 0..127], stride 136
    float* W1T   = s2 + W1T_OFF;   // [k 0..255][rl], rows 0..127 = w_ih1, 128..255 = w_hh1
    float* Hbuf  = s2 + H_OFF;     // [buf][k][b] : buf*2048 + k*8 + b
    float* gates = s2 + GT_OFF;    // [b][rl] : b*128 + rl
    float* bias1 = s2 + B1_OFF;    // [rl]

    const int tid = threadIdx.x;
    uint32_t rank;
    asm("mov.u32 %0, %%cluster_ctarank;" : "=r"(rank));
    const int irank = (int)rank;
    const int cbase = (blockIdx.x >> 2) * BPC;

    // ---- prologue: load own weight slices, transposed ----
    for (int idx = tid; idx < 128 * 128; idx += SC_THREADS) {
        int rl = idx >> 7, k = idx & 127;
        int grow = ((rl >> 5) << 7) + irank * 32 + (rl & 31);
        W0T[k * WSTRIDE + rl]         = w_hh0[grow * H_ + k];
        W1T[k * WSTRIDE + rl]         = w_ih1[grow * H_ + k];
        W1T[(128 + k) * WSTRIDE + rl] = w_hh1[grow * H_ + k];
    }
    for (int rl = tid; rl < 128; rl += SC_THREADS) {
        int grow = ((rl >> 5) << 7) + irank * 32 + (rl & 31);
        bias1[rl] = b_ih1[grow] + b_hh1[grow];
    }
    for (int i = tid; i < 2 * 256 * 8; i += SC_THREADS) Hbuf[i] = 0.0f;

    // remote smem base addresses of Hbuf for all 4 ranks
    uint32_t hloc = smem_u32(Hbuf);
    uint32_t hrem[4];
    #pragma unroll
    for (int r = 0; r < 4; ++r) hrem[r] = mapa_u32(hloc, (uint32_t)r);

    CLUSTER_SYNC();

    // GEMM thread mapping: 256 threads = 64 tiles x 4 k-chunks
    const int kc = tid & 3;          // k-chunk (interleaved: k = 4*ii + kc)
    const int tl = tid >> 2;
    const int rg = tl & 31;          // rows rg*4 .. rg*4+3 (of 128 local gate rows)
    const int bg = tl >> 5;          // batches bg*4 .. bg*4+3 (of 8)
    // elementwise mapping: thread <-> (batch eb, own col ej)
    const int eb = tid >> 5;         // 0..7
    const int ej = tid & 31;         // 0..31
    const float* xgbase = g_xg0 + (size_t)(cbase + eb) * G_ + irank * 32 + ej;

    float c0 = 0.0f, c1 = 0.0f;

    for (int t = 0; t < T_; ++t) {
        const int p = t & 1;
        // prefetch xg for this (b, col): gates i,f,g,o at +0,+128,+256,+384
        const float* xgp = xgbase + (size_t)t * (B_ * G_);
        float xg_i = __ldg(xgp);
        float xg_f = __ldg(xgp + 128);
        float xg_g = __ldg(xgp + 256);
        float xg_o = __ldg(xgp + 384);

        // ---- GEMM0: gates0 = W0 @ h0_prev ----
        {
            const float* hb = Hbuf + (p << 11);   // H[p][0..127][.]
            float a[4][4];
            #pragma unroll
            for (int r = 0; r < 4; ++r)
                #pragma unroll
                for (int b = 0; b < 4; ++b) a[r][b] = 0.0f;
            #pragma unroll 8
            for (int ii = 0; ii < 32; ++ii) {
                int k = (ii << 2) + kc;
                float4 w = *reinterpret_cast<const float4*>(W0T + k * WSTRIDE + (rg << 2));
                float4 h = *reinterpret_cast<const float4*>(hb + (k << 3) + (bg << 2));
                a[0][0] += w.x*h.x; a[0][1] += w.x*h.y; a[0][2] += w.x*h.z; a[0][3] += w.x*h.w;
                a[1][0] += w.y*h.x; a[1][1] += w.y*h.y; a[1][2] += w.y*h.z; a[1][3] += w.y*h.w;
                a[2][0] += w.z*h.x; a[2][1] += w.z*h.y; a[2][2] += w.z*h.z; a[2][3] += w.z*h.w;
                a[3][0] += w.w*h.x; a[3][1] += w.w*h.y; a[3][2] += w.w*h.z; a[3][3] += w.w*h.w;
            }
            #pragma unroll
            for (int r = 0; r < 4; ++r)
                #pragma unroll
                for (int b = 0; b < 4; ++b) {
                    float v = a[r][b];
                    v += __shfl_xor_sync(0xffffffffu, v, 1);
                    v += __shfl_xor_sync(0xffffffffu, v, 2);
                    a[r][b] = v;
                }
            if (kc == 0) {
                #pragma unroll
                for (int r = 0; r < 4; ++r)
                    #pragma unroll
                    for (int b = 0; b < 4; ++b)
                        gates[(((bg << 2) + b) << 7) + (rg << 2) + r] = a[r][b];
            }
        }
        __syncthreads();

        // ---- elementwise layer 0 -> h0_new, broadcast to cluster ----
        {
            float gi = gates[(eb << 7) + ej]      + xg_i;
            float gf = gates[(eb << 7) + 32 + ej] + xg_f;
            float gg = gates[(eb << 7) + 64 + ej] + xg_g;
            float go = gates[(eb << 7) + 96 + ej] + xg_o;
            float iv = sigf(gi), fv = sigf(gf), gv = tanh_f(gg), ov = sigf(go);
            c0 = fv * c0 + iv * gv;
            float h0 = ov * tanh_f(c0);
            uint32_t off = (uint32_t)((((1 - p) << 11) + ((irank * 32 + ej) << 3) + eb) << 2);
            #pragma unroll
            for (int r = 0; r < 4; ++r) stc_f32(hrem[r] + off, h0);
        }
        CLUSTER_SYNC();

        // ---- GEMM1: gates1 = W_ih1 @ h0_new + W_hh1 @ h1_prev (K=256) ----
        {
            const float* hbA = Hbuf + ((1 - p) << 11);  // h0_new at rows 0..127
            const float* hbB = Hbuf + (p << 11);        // h1_prev at rows 128..255
            float a[4][4];
            #pragma unroll
            for (int r = 0; r < 4; ++r)
                #pragma unroll
                for (int b = 0; b < 4; ++b) a[r][b] = 0.0f;
            #pragma unroll 8
            for (int ii = 0; ii < 32; ++ii) {
                int k = (ii << 2) + kc;
                float4 w = *reinterpret_cast<const float4*>(W1T + k * WSTRIDE + (rg << 2));
                float4 h = *reinterpret_cast<const float4*>(hbA + (k << 3) + (bg << 2));
                a[0][0] += w.x*h.x; a[0][1] += w.x*h.y; a[0][2] += w.x*h.z; a[0][3] += w.x*h.w;
                a[1][0] += w.y*h.x; a[1][1] += w.y*h.y; a[1][2] += w.y*h.z; a[1][3] += w.y*h.w;
                a[2][0] += w.z*h.x; a[2][1] += w.z*h.y; a[2][2] += w.z*h.z; a[2][3] += w.z*h.w;
                a[3][0] += w.w*h.x; a[3][1] += w.w*h.y; a[3][2] += w.w*h.z; a[3][3] += w.w*h.w;
            }
            #pragma unroll 8
            for (int ii = 32; ii < 64; ++ii) {
                int k = (ii << 2) + kc;                 // 128..255
                float4 w = *reinterpret_cast<const float4*>(W1T + k * WSTRIDE + (rg << 2));
                float4 h = *reinterpret_cast<const float4*>(hbB + (k << 3) + (bg << 2));
                a[0][0] += w.x*h.x; a[0][1] += w.x*h.y; a[0][2] += w.x*h.z; a[0][3] += w.x*h.w;
                a[1][0] += w.y*h.x; a[1][1] += w.y*h.y; a[1][2] += w.y*h.z; a[1][3] += w.y*h.w;
                a[2][0] += w.z*h.x; a[2][1] += w.z*h.y; a[2][2] += w.z*h.z; a[2][3] += w.z*h.w;
                a[3][0] += w.w*h.x; a[3][1] += w.w*h.y; a[3][2] += w.w*h.z; a[3][3] += w.w*h.w;
            }
            #pragma unroll
            for (int r = 0; r < 4; ++r)
                #pragma unroll
                for (int b = 0; b < 4; ++b) {
                    float v = a[r][b];
                    v += __shfl_xor_sync(0xffffffffu, v, 1);
                    v += __shfl_xor_sync(0xffffffffu, v, 2);
                    a[r][b] = v;
                }
            if (kc == 0) {
                #pragma unroll
                for (int r = 0; r < 4; ++r)
                    #pragma unroll
                    for (int b = 0; b < 4; ++b)
                        gates[(((bg << 2) + b) << 7) + (rg << 2) + r] = a[r][b];
            }
        }
        __syncthreads();

        // ---- elementwise layer 1 -> h1_new, broadcast to cluster ----
        {
            float gi = gates[(eb << 7) + ej]      + bias1[ej];
            float gf = gates[(eb << 7) + 32 + ej] + bias1[32 + ej];
            float gg = gates[(eb << 7) + 64 + ej] + bias1[64 + ej];
            float go = gates[(eb << 7) + 96 + ej] + bias1[96 + ej];
            float iv = sigf(gi), fv = sigf(gf), gv = tanh_f(gg), ov = sigf(go);
            c1 = fv * c1 + iv * gv;
            float h1 = ov * tanh_f(c1);
            uint32_t off = (uint32_t)((((1 - p) << 11) + ((128 + irank * 32 + ej) << 3) + eb) << 2);
            #pragma unroll
            for (int r = 0; r < 4; ++r) stc_f32(hrem[r] + off, h1);
        }
        CLUSTER_SYNC();
    }

    // ---- epilogue: out[b] = fc_b + sum_c h1_last[b][c] * fc_w[c] ----
    // t=511 had p=1, so final h1 lives in buffer 0, rows 128..255.
    if (rank == 0) {
        const int b = tid >> 5;
        const int l = tid & 31;
        const float* h1p = Hbuf;   // buffer 0
        float ssum = 0.0f;
        #pragma unroll
        for (int cc = 0; cc < 4; ++cc) {
            int c = l * 4 + cc;
            ssum += h1p[((128 + c) << 3) + b] * __ldg(fc_w + c);
        }
        #pragma unroll
        for (int d = 16; d > 0; d >>= 1)
            ssum += __shfl_xor_sync(0xffffffffu, ssum, d);
        if (l == 0) out[cbase + b] = ssum + __ldg(fc_b);
    }
    CLUSTER_SYNC();
}

// ---------------------------------------------------------------------------
extern "C" void kernel_launch(void* const* d_in, const int* in_sizes, int n_in,
                              void* d_out, int out_size)
{
    const float* x     = (const float*)d_in[0];
    const float* w_ih0 = (const float*)d_in[1];
    const float* w_hh0 = (const float*)d_in[2];
    const float* b_ih0 = (const float*)d_in[3];
    const float* b_hh0 = (const float*)d_in[4];
    const float* w_ih1 = (const float*)d_in[5];
    const float* w_hh1 = (const float*)d_in[6];
    const float* b_ih1 = (const float*)d_in[7];
    const float* b_hh1 = (const float*)d_in[8];
    const float* fc_w  = (const float*)d_in[9];
    const float* fc_b  = (const float*)d_in[10];
    float* out = (float*)d_out;

    const int p1_smem = P1_SMEM_FLOATS * 4;
    const int sc_smem = SC_SMEM_FLOATS * 4;
    cudaFuncSetAttribute(p1_kernel,  cudaFuncAttributeMaxDynamicSharedMemorySize, p1_smem);
    cudaFuncSetAttribute(scan_kernel, cudaFuncAttributeMaxDynamicSharedMemorySize, sc_smem);

    // Phase 1: input projections for layer 0 (parallel over all timesteps)
    p1_kernel<<<(B_ * T_) / P1_ROWS, P1_THREADS, p1_smem>>>(x, w_ih0, b_ih0, b_hh0);
    // Phase 2: fused 2-layer sequential scan + FC head
    scan_kernel<<<(B_ / BPC) * CL_N, SC_THREADS, sc_smem>>>(
        w_hh0, w_ih1, w_hh1, b_ih1, b_hh1, fc_w, fc_b, out);
}

// round 3
// speedup vs baseline: 1.2336x; 1.2128x over previous
#include <cuda_runtime.h>
#include <cstdint>

typedef unsigned long long ull;

#define B_   256
#define T_   512
#define IN_  64
#define H_   128
#define G_   512   // 4*H

// scratch for precomputed layer-0 input projections, layout [t][b][g]
__device__ float g_xg0[(size_t)T_ * B_ * G_];

// ---------------------------------------------------------------------------
// helpers
// ---------------------------------------------------------------------------
__device__ __forceinline__ uint32_t smem_u32(const void* p) {
    uint32_t a;
    asm("{ .reg .u64 t; cvta.to.shared.u64 t, %1; cvt.u32.u64 %0, t; }"
        : "=r"(a) : "l"(p));
    return a;
}
__device__ __forceinline__ uint32_t mapa_u32(uint32_t addr, uint32_t rank) {
    uint32_t r;
    asm("mapa.shared::cluster.u32 %0, %1, %2;" : "=r"(r) : "r"(addr), "r"(rank));
    return r;
}
__device__ __forceinline__ void stc_f32(uint32_t addr, float v) {
    asm volatile("st.shared::cluster.f32 [%0], %1;" :: "r"(addr), "f"(v));
}
#define CLUSTER_SYNC() do { \
    asm volatile("barrier.cluster.arrive.aligned;" ::: "memory"); \
    asm volatile("barrier.cluster.wait.aligned;"   ::: "memory"); \
} while (0)

__device__ __forceinline__ float sigf(float x)  { return 1.0f / (1.0f + __expf(-x)); }
__device__ __forceinline__ float tanh_f(float x){ return 1.0f - 2.0f / (__expf(2.0f * x) + 1.0f); }

// ---- packed f32x2 (Blackwell) ----
__device__ __forceinline__ ull ffma2(ull a, ull b, ull c) {
    ull d;
    asm("fma.rn.f32x2 %0, %1, %2, %3;" : "=l"(d) : "l"(a), "l"(b), "l"(c));
    return d;
}
__device__ __forceinline__ ull add2(ull a, ull b) {
    ull c;
    asm("add.rn.f32x2 %0, %1, %2;" : "=l"(c) : "l"(a), "l"(b));
    return c;
}
__device__ __forceinline__ ull pack2(float x) {
    ull r;
    asm("mov.b64 %0, {%1, %1};" : "=l"(r) : "f"(x));
    return r;
}
__device__ __forceinline__ float2 unpack2(ull v) {
    float2 f;
    asm("mov.b64 {%0, %1}, %2;" : "=f"(f.x), "=f"(f.y) : "l"(v));
    return f;
}

// ---------------------------------------------------------------------------
// Phase 1: xg0[t][b][g] = (b_ih0+b_hh0)[g] + sum_i x[b][t][i] * w_ih0[g][i]
// row n = b*T + t. Block: 64 rows x 512 cols. f32x2 packed math.
// ---------------------------------------------------------------------------
#define P1_ROWS    64
#define P1_THREADS 256
#define P1_XT_STRIDE 68
#define P1_WT_OFF   0
#define P1_XT_OFF   (64*512)
#define P1_B_OFF    (P1_XT_OFF + 64*P1_XT_STRIDE)
#define P1_SMEM_FLOATS (P1_B_OFF + 512)

__global__ void __launch_bounds__(P1_THREADS)
p1_kernel(const float* __restrict__ x,
          const float* __restrict__ w_ih0,
          const float* __restrict__ b_ih0,
          const float* __restrict__ b_hh0)
{
    extern __shared__ float s1[];
    float* WT   = s1 + P1_WT_OFF;   // [k][g], stride 512
    float* xT   = s1 + P1_XT_OFF;   // [k][row], stride 68
    float* bias = s1 + P1_B_OFF;

    const int tid     = threadIdx.x;
    const int rowbase = blockIdx.x * P1_ROWS;

    for (int idx = tid; idx < G_ * IN_; idx += P1_THREADS) {
        int g = idx >> 6, k = idx & 63;
        WT[k * 512 + g] = w_ih0[idx];
    }
    for (int g = tid; g < G_; g += P1_THREADS)
        bias[g] = b_ih0[g] + b_hh0[g];
    for (int idx = tid; idx < P1_ROWS * IN_ / 4; idx += P1_THREADS) {
        int row = idx >> 4, kq = idx & 15;
        float4 v = reinterpret_cast<const float4*>(x + (size_t)(rowbase + row) * IN_)[kq];
        int k = kq * 4;
        xT[(k + 0) * P1_XT_STRIDE + row] = v.x;
        xT[(k + 1) * P1_XT_STRIDE + row] = v.y;
        xT[(k + 2) * P1_XT_STRIDE + row] = v.z;
        xT[(k + 3) * P1_XT_STRIDE + row] = v.w;
    }
    __syncthreads();

    const int cg  = tid & 63;   // col group: cols 4cg..4cg+3 (both halves)
    const int rgq = tid >> 6;   // 0..3

    for (int it = 0; it < 4; ++it) {
        const int rg = it * 4 + rgq;
        ull a2[4][4];
        #pragma unroll
        for (int r = 0; r < 4; ++r)
            #pragma unroll
            for (int c = 0; c < 4; ++c) a2[r][c] = 0ull;

        #pragma unroll 4
        for (int k = 0; k < IN_; ++k) {
            float4 xv = *reinterpret_cast<const float4*>(xT + k * P1_XT_STRIDE + (rg << 2));
            ulonglong2 w0 = *reinterpret_cast<const ulonglong2*>(WT + (k << 9) + (cg << 2));
            ulonglong2 w1 = *reinterpret_cast<const ulonglong2*>(WT + (k << 9) + 256 + (cg << 2));
            ull xd0 = pack2(xv.x), xd1 = pack2(xv.y), xd2 = pack2(xv.z), xd3 = pack2(xv.w);
            a2[0][0] = ffma2(xd0, w0.x, a2[0][0]); a2[0][1] = ffma2(xd0, w0.y, a2[0][1]);
            a2[0][2] = ffma2(xd0, w1.x, a2[0][2]); a2[0][3] = ffma2(xd0, w1.y, a2[0][3]);
            a2[1][0] = ffma2(xd1, w0.x, a2[1][0]); a2[1][1] = ffma2(xd1, w0.y, a2[1][1]);
            a2[1][2] = ffma2(xd1, w1.x, a2[1][2]); a2[1][3] = ffma2(xd1, w1.y, a2[1][3]);
            a2[2][0] = ffma2(xd2, w0.x, a2[2][0]); a2[2][1] = ffma2(xd2, w0.y, a2[2][1]);
            a2[2][2] = ffma2(xd2, w1.x, a2[2][2]); a2[2][3] = ffma2(xd2, w1.y, a2[2][3]);
            a2[3][0] = ffma2(xd3, w0.x, a2[3][0]); a2[3][1] = ffma2(xd3, w0.y, a2[3][1]);
            a2[3][2] = ffma2(xd3, w1.x, a2[3][2]); a2[3][3] = ffma2(xd3, w1.y, a2[3][3]);
        }
        float4 bb0 = *reinterpret_cast<const float4*>(bias + (cg << 2));
        float4 bb1 = *reinterpret_cast<const float4*>(bias + 256 + (cg << 2));
        #pragma unroll
        for (int r = 0; r < 4; ++r) {
            int n = rowbase + rg * 4 + r;
            int b = n >> 9;          // T = 512
            int t = n & 511;
            float* op = g_xg0 + ((size_t)t * B_ + b) * G_;
            float2 p0 = unpack2(a2[r][0]), p1v = unpack2(a2[r][1]);
            float2 p2 = unpack2(a2[r][2]), p3v = unpack2(a2[r][3]);
            float4 o0 = make_float4(p0.x + bb0.x, p0.y + bb0.y, p1v.x + bb0.z, p1v.y + bb0.w);
            float4 o1 = make_float4(p2.x + bb1.x, p2.y + bb1.y, p3v.x + bb1.z, p3v.y + bb1.w);
            *reinterpret_cast<float4*>(op + (cg << 2))       = o0;
            *reinterpret_cast<float4*>(op + 256 + (cg << 2)) = o1;
        }
    }
}

// ---------------------------------------------------------------------------
// Phase 2: persistent fused 2-layer scan, f32x2 packed math.
// 32 clusters x 4 CTAs, 8 batches/cluster, 512 threads/CTA.
// CTA rank r owns hidden cols [r*32, r*32+32) (gate rows q*128 + r*32 + j).
// GEMM: 16-way k-split (kc = tid&15); per 16-lane group an 8-row x 4-batch
// tile (tile = tid>>4: bg = tile&1, rg = tile>>1). W k-major stride 128
// with 16B-group XOR swizzle (^ (k&7)); rows packed pairwise for FFMA2.
// H [buf][k][b] stride 12 (phase-conflict-free). Fold-exchange reduction.
// ONE cluster barrier per step (mid-step); __syncthreads elsewhere.
// ---------------------------------------------------------------------------
#define SC_THREADS 512
#define CL_N 4
#define BPC  8
#define HS   12
#define GS   9
#define W0T_OFF 0
#define W1T_OFF 16384
#define H_OFF   49152                 // 2 bufs * 256 k * 12
#define GT_OFF  55296                 // 128*9
#define B1_OFF  56448
#define SC_SMEM_FLOATS 56576          // 226304 B

// one K-half (8 k-iters) of a GEMM into flat acc[(rp<<2)|b]
__device__ __forceinline__ void gemm_half(const float* __restrict__ Wb,
                                          const float* __restrict__ hb,
                                          int kc, int rg, int bg, int k0,
                                          ull acc[16])
{
    #pragma unroll
    for (int ii = 0; ii < 8; ++ii) {
        int k = k0 + (ii << 4) + kc;
        const float* wr = Wb + (k << 7);
        int sw = k & 7;
        ulonglong2 wA = *reinterpret_cast<const ulonglong2*>(wr + ((((rg << 1)    ) ^ sw) << 2));
        ulonglong2 wB = *reinterpret_cast<const ulonglong2*>(wr + ((((rg << 1) | 1) ^ sw) << 2));
        float4 h = *reinterpret_cast<const float4*>(hb + k * HS + (bg << 2));
        ull h0 = pack2(h.x), h1 = pack2(h.y), h2 = pack2(h.z), h3 = pack2(h.w);
        acc[ 0] = ffma2(wA.x, h0, acc[ 0]); acc[ 1] = ffma2(wA.x, h1, acc[ 1]);
        acc[ 2] = ffma2(wA.x, h2, acc[ 2]); acc[ 3] = ffma2(wA.x, h3, acc[ 3]);
        acc[ 4] = ffma2(wA.y, h0, acc[ 4]); acc[ 5] = ffma2(wA.y, h1, acc[ 5]);
        acc[ 6] = ffma2(wA.y, h2, acc[ 6]); acc[ 7] = ffma2(wA.y, h3, acc[ 7]);
        acc[ 8] = ffma2(wB.x, h0, acc[ 8]); acc[ 9] = ffma2(wB.x, h1, acc[ 9]);
        acc[10] = ffma2(wB.x, h2, acc[10]); acc[11] = ffma2(wB.x, h3, acc[11]);
        acc[12] = ffma2(wB.y, h0, acc[12]); acc[13] = ffma2(wB.y, h1, acc[13]);
        acc[14] = ffma2(wB.y, h2, acc[14]); acc[15] = ffma2(wB.y, h3, acc[15]);
    }
}

// fold-exchange reduction over the 16 kc lanes, then store this lane's
// f32x2 (rows row0, row0+1 of one batch) to gates.
__device__ __forceinline__ void fold_store(ull F[16], float* __restrict__ gates,
                                           int kc, int rg, int bg)
{
    {   // D=1: keep 8
        const bool hi = kc & 1;
        #pragma unroll
        for (int i = 0; i < 8; ++i) {
            ull give = hi ? F[i] : F[i + 8];
            ull keep = hi ? F[i + 8] : F[i];
            F[i] = add2(keep, __shfl_xor_sync(0xffffffffu, give, 1));
        }
    }
    {   // D=2: keep 4
        const bool hi = kc & 2;
        #pragma unroll
        for (int i = 0; i < 4; ++i) {
            ull give = hi ? F[i] : F[i + 4];
            ull keep = hi ? F[i + 4] : F[i];
            F[i] = add2(keep, __shfl_xor_sync(0xffffffffu, give, 2));
        }
    }
    {   // D=4: keep 2
        const bool hi = kc & 4;
        #pragma unroll
        for (int i = 0; i < 2; ++i) {
            ull give = hi ? F[i] : F[i + 2];
            ull keep = hi ? F[i + 2] : F[i];
            F[i] = add2(keep, __shfl_xor_sync(0xffffffffu, give, 4));
        }
    }
    {   // D=8: keep 1
        const bool hi = kc & 8;
        ull give = hi ? F[0] : F[1];
        ull keep = hi ? F[1] : F[0];
        F[0] = add2(keep, __shfl_xor_sync(0xffffffffu, give, 8));
    }
    // lane kc holds flat index bitrev4(kc) = (rp<<2)|b
    const int rp = ((kc & 1) << 1) | ((kc >> 1) & 1);
    const int bb = (((kc >> 2) & 1) << 1) | ((kc >> 3) & 1);
    const int row0 = (rg << 3) + (rp << 1);
    float2 v = unpack2(F[0]);
    gates[row0 * GS + (bg << 2) + bb]       = v.x;
    gates[(row0 + 1) * GS + (bg << 2) + bb] = v.y;
}

__global__ void __launch_bounds__(SC_THREADS, 1) __cluster_dims__(CL_N, 1, 1)
scan_kernel(const float* __restrict__ w_hh0,
            const float* __restrict__ w_ih1,
            const float* __restrict__ w_hh1,
            const float* __restrict__ b_ih1,
            const float* __restrict__ b_hh1,
            const float* __restrict__ fc_w,
            const float* __restrict__ fc_b,
            float* __restrict__ out)
{
    extern __shared__ float s2[];
    float* W0T   = s2 + W0T_OFF;   // [k 0..127][rl], swizzled, stride 128
    float* W1T   = s2 + W1T_OFF;   // [k 0..255][rl]: 0..127 w_ih1, 128.. w_hh1
    float* Hbuf  = s2 + H_OFF;     // [buf][k 0..255][b], stride HS; k<128 h0, else h1
    float* gates = s2 + GT_OFF;    // [rl][b], stride GS
    float* bias1 = s2 + B1_OFF;

    const int tid = threadIdx.x;
    uint32_t rank;
    asm("mov.u32 %0, %%cluster_ctarank;" : "=r"(rank));
    const int irank = (int)rank;
    const int cbase = (blockIdx.x >> 2) * BPC;

    // ---- prologue: own weight slices, k-major + XOR swizzle ----
    for (int idx = tid; idx < 128 * 128; idx += SC_THREADS) {
        int rl = idx >> 7, k = idx & 127;
        int grow = ((rl >> 5) << 7) + irank * 32 + (rl & 31);
        int sa = (((rl >> 2) ^ (k & 7)) << 2) + (rl & 3);
        W0T[(k << 7) + sa]         = w_hh0[grow * H_ + k];
        W1T[(k << 7) + sa]         = w_ih1[grow * H_ + k];
        W1T[((128 + k) << 7) + sa] = w_hh1[grow * H_ + k];   // (128+k)&7 == k&7
    }
    for (int rl = tid; rl < 128; rl += SC_THREADS) {
        int grow = ((rl >> 5) << 7) + irank * 32 + (rl & 31);
        bias1[rl] = b_ih1[grow] + b_hh1[grow];
    }
    for (int i = tid; i < 2 * 256 * HS; i += SC_THREADS) Hbuf[i] = 0.0f;

    const uint32_t hloc = smem_u32(Hbuf);
    uint32_t hrem[4];
    #pragma unroll
    for (int r = 0; r < 4; ++r) hrem[r] = mapa_u32(hloc, (uint32_t)r);

    CLUSTER_SYNC();

    // GEMM mapping
    const int kc = tid & 15;
    const int tl = tid >> 4;         // 0..31
    const int bg = tl & 1;           // batches bg*4..+3
    const int rg = tl >> 1;          // rows rg*8..+7 (== warp id)
    // elementwise mapping (tid < 256)
    const int eb  = tid >> 5;        // batch 0..7
    const int ej  = tid & 31;        // own col 0..31
    const int col = irank * 32 + ej;
    const float* xgbase = g_xg0 + (size_t)(cbase + eb) * G_ + col;

    float c0 = 0.0f, c1 = 0.0f;

    for (int t = 0; t < T_; ++t) {
        const int p = t & 1;
        float xg_i = 0.f, xg_f = 0.f, xg_g = 0.f, xg_o = 0.f;
        if (tid < 256) {
            const float* xgp = xgbase + (size_t)t * (B_ * G_);
            xg_i = __ldg(xgp);
            xg_f = __ldg(xgp + 128);
            xg_g = __ldg(xgp + 256);
            xg_o = __ldg(xgp + 384);
        }

        // ---- GEMM0: gates0 = W_hh0 @ h0_prev ----
        {
            ull acc[16];
            #pragma unroll
            for (int i = 0; i < 16; ++i) acc[i] = 0ull;
            gemm_half(W0T, Hbuf + (p ? 3072 : 0), kc, rg, bg, 0, acc);
            fold_store(acc, gates, kc, rg, bg);
        }
        __syncthreads();

        // ---- elementwise layer 0 -> h0_new, broadcast ----
        if (tid < 256) {
            float gi = gates[ej * GS + eb]        + xg_i;
            float gf = gates[(32 + ej) * GS + eb] + xg_f;
            float gg = gates[(64 + ej) * GS + eb] + xg_g;
            float go = gates[(96 + ej) * GS + eb] + xg_o;
            float iv = sigf(gi), fv = sigf(gf), gv = tanh_f(gg), ov = sigf(go);
            c0 = fv * c0 + iv * gv;
            float h0 = ov * tanh_f(c0);
            uint32_t off = (uint32_t)((((1 - p) ? 3072 : 0) + col * HS + eb) << 2);
            #pragma unroll
            for (int r = 0; r < 4; ++r) stc_f32(hrem[r] + off, h0);
        }
        CLUSTER_SYNC();   // h0_new visible cluster-wide; also orders gates WAR

        // ---- GEMM1: gates1 = W_ih1 @ h0_new + W_hh1 @ h1_prev ----
        {
            ull acc[16];
            #pragma unroll
            for (int i = 0; i < 16; ++i) acc[i] = 0ull;
            gemm_half(W1T, Hbuf + ((1 - p) ? 3072 : 0), kc, rg, bg, 0,   acc); // h0_new, k 0..127
            gemm_half(W1T, Hbuf + (p ? 3072 : 0),       kc, rg, bg, 128, acc); // h1_prev, k 128..255
            fold_store(acc, gates, kc, rg, bg);
        }
        __syncthreads();

        // ---- elementwise layer 1 -> h1_new, broadcast ----
        if (tid < 256) {
            float gi = gates[ej * GS + eb]        + bias1[ej];
            float gf = gates[(32 + ej) * GS + eb] + bias1[32 + ej];
            float gg = gates[(64 + ej) * GS + eb] + bias1[64 + ej];
            float go = gates[(96 + ej) * GS + eb] + bias1[96 + ej];
            float iv = sigf(gi), fv = sigf(gf), gv = tanh_f(gg), ov = sigf(go);
            c1 = fv * c1 + iv * gv;
            float h1 = ov * tanh_f(c1);
            uint32_t off = (uint32_t)((((1 - p) ? 3072 : 0) + (128 + col) * HS + eb) << 2);
            #pragma unroll
            for (int r = 0; r < 4; ++r) stc_f32(hrem[r] + off, h1);
        }
        __syncthreads();  // local gates WAR vs next step's GEMM0 stores
        // (cross-CTA h hazards for the next step are ordered by its mid barrier)
    }

    CLUSTER_SYNC();   // final remote h1 writes (t=511 -> buf 0) must land

    // ---- epilogue: out[b] = fc_b + sum_c h1_last[b][c] * fc_w[c] ----
    if (irank == 0 && tid < 256) {
        const int b = tid >> 5;
        const int l = tid & 31;
        float ssum = 0.0f;
        #pragma unroll
        for (int cc = 0; cc < 4; ++cc) {
            int c = l * 4 + cc;
            ssum += Hbuf[(128 + c) * HS + b] * __ldg(fc_w + c);   // buf 0
        }
        #pragma unroll
        for (int d = 16; d > 0; d >>= 1)
            ssum += __shfl_xor_sync(0xffffffffu, ssum, d);
        if (l == 0) out[cbase + b] = ssum + __ldg(fc_b);
    }
    CLUSTER_SYNC();
}

// ---------------------------------------------------------------------------
extern "C" void kernel_launch(void* const* d_in, const int* in_sizes, int n_in,
                              void* d_out, int out_size)
{
    const float* x     = (const float*)d_in[0];
    const float* w_ih0 = (const float*)d_in[1];
    const float* w_hh0 = (const float*)d_in[2];
    const float* b_ih0 = (const float*)d_in[3];
    const float* b_hh0 = (const float*)d_in[4];
    const float* w_ih1 = (const float*)d_in[5];
    const float* w_hh1 = (const float*)d_in[6];
    const float* b_ih1 = (const float*)d_in[7];
    const float* b_hh1 = (const float*)d_in[8];
    const float* fc_w  = (const float*)d_in[9];
    const float* fc_b  = (const float*)d_in[10];
    float* out = (float*)d_out;

    const int p1_smem = P1_SMEM_FLOATS * 4;
    const int sc_smem = SC_SMEM_FLOATS * 4;
    cudaFuncSetAttribute(p1_kernel,   cudaFuncAttributeMaxDynamicSharedMemorySize, p1_smem);
    cudaFuncSetAttribute(scan_kernel, cudaFuncAttributeMaxDynamicSharedMemorySize, sc_smem);

    p1_kernel<<<(B_ * T_) / P1_ROWS, P1_THREADS, p1_smem>>>(x, w_ih0, b_ih0, b_hh0);
    scan_kernel<<<(B_ / BPC) * CL_N, SC_THREADS, sc_smem>>>(
        w_hh0, w_ih1, w_hh1, b_ih1, b_hh1, fc_w, fc_b, out);
}

// round 4
// speedup vs baseline: 1.2474x; 1.0112x over previous
#include <cuda_runtime.h>
#include <cstdint>

typedef unsigned long long ull;

#define B_   256
#define T_   512
#define IN_  64
#define H_   128
#define G_   512   // 4*H

// scratch for precomputed layer-0 input projections, layout [t][b][g]
__device__ float g_xg0[(size_t)T_ * B_ * G_];

// ---------------------------------------------------------------------------
// helpers
// ---------------------------------------------------------------------------
__device__ __forceinline__ uint32_t smem_u32(const void* p) {
    uint32_t a;
    asm("{ .reg .u64 t; cvta.to.shared.u64 t, %1; cvt.u32.u64 %0, t; }"
        : "=r"(a) : "l"(p));
    return a;
}
__device__ __forceinline__ uint32_t mapa_u32(uint32_t addr, uint32_t rank) {
    uint32_t r;
    asm("mapa.shared::cluster.u32 %0, %1, %2;" : "=r"(r) : "r"(addr), "r"(rank));
    return r;
}
__device__ __forceinline__ void stc_f32(uint32_t addr, float v) {
    asm volatile("st.shared::cluster.f32 [%0], %1;" :: "r"(addr), "f"(v));
}
#define CLUSTER_ARRIVE() asm volatile("barrier.cluster.arrive.aligned;" ::: "memory")
#define CLUSTER_WAIT()   asm volatile("barrier.cluster.wait.aligned;"   ::: "memory")
#define CLUSTER_SYNC() do { CLUSTER_ARRIVE(); CLUSTER_WAIT(); } while (0)

__device__ __forceinline__ float sigf(float x)  { return 1.0f / (1.0f + __expf(-x)); }
__device__ __forceinline__ float tanh_f(float x){ return 1.0f - 2.0f / (__expf(2.0f * x) + 1.0f); }

// ---- packed f32x2 (Blackwell) ----
__device__ __forceinline__ ull ffma2(ull a, ull b, ull c) {
    ull d;
    asm("fma.rn.f32x2 %0, %1, %2, %3;" : "=l"(d) : "l"(a), "l"(b), "l"(c));
    return d;
}
__device__ __forceinline__ ull add2(ull a, ull b) {
    ull c;
    asm("add.rn.f32x2 %0, %1, %2;" : "=l"(c) : "l"(a), "l"(b));
    return c;
}
__device__ __forceinline__ ull pack2(float x) {
    ull r;
    asm("mov.b64 %0, {%1, %1};" : "=l"(r) : "f"(x));
    return r;
}
__device__ __forceinline__ float2 unpack2(ull v) {
    float2 f;
    asm("mov.b64 {%0, %1}, %2;" : "=f"(f.x), "=f"(f.y) : "l"(v));
    return f;
}

// ---------------------------------------------------------------------------
// Phase 1: xg0[t][b][g] = (b_ih0+b_hh0)[g] + sum_i x[b][t][i] * w_ih0[g][i]
// ---------------------------------------------------------------------------
#define P1_ROWS    64
#define P1_THREADS 256
#define P1_XT_STRIDE 68
#define P1_WT_OFF   0
#define P1_XT_OFF   (64*512)
#define P1_B_OFF    (P1_XT_OFF + 64*P1_XT_STRIDE)
#define P1_SMEM_FLOATS (P1_B_OFF + 512)

__global__ void __launch_bounds__(P1_THREADS)
p1_kernel(const float* __restrict__ x,
          const float* __restrict__ w_ih0,
          const float* __restrict__ b_ih0,
          const float* __restrict__ b_hh0)
{
    extern __shared__ float s1[];
    float* WT   = s1 + P1_WT_OFF;
    float* xT   = s1 + P1_XT_OFF;
    float* bias = s1 + P1_B_OFF;

    const int tid     = threadIdx.x;
    const int rowbase = blockIdx.x * P1_ROWS;

    for (int idx = tid; idx < G_ * IN_; idx += P1_THREADS) {
        int g = idx >> 6, k = idx & 63;
        WT[k * 512 + g] = w_ih0[idx];
    }
    for (int g = tid; g < G_; g += P1_THREADS)
        bias[g] = b_ih0[g] + b_hh0[g];
    for (int idx = tid; idx < P1_ROWS * IN_ / 4; idx += P1_THREADS) {
        int row = idx >> 4, kq = idx & 15;
        float4 v = reinterpret_cast<const float4*>(x + (size_t)(rowbase + row) * IN_)[kq];
        int k = kq * 4;
        xT[(k + 0) * P1_XT_STRIDE + row] = v.x;
        xT[(k + 1) * P1_XT_STRIDE + row] = v.y;
        xT[(k + 2) * P1_XT_STRIDE + row] = v.z;
        xT[(k + 3) * P1_XT_STRIDE + row] = v.w;
    }
    __syncthreads();

    const int cg  = tid & 63;
    const int rgq = tid >> 6;

    for (int it = 0; it < 4; ++it) {
        const int rg = it * 4 + rgq;
        ull a2[4][4];
        #pragma unroll
        for (int r = 0; r < 4; ++r)
            #pragma unroll
            for (int c = 0; c < 4; ++c) a2[r][c] = 0ull;

        #pragma unroll 4
        for (int k = 0; k < IN_; ++k) {
            float4 xv = *reinterpret_cast<const float4*>(xT + k * P1_XT_STRIDE + (rg << 2));
            ulonglong2 w0 = *reinterpret_cast<const ulonglong2*>(WT + (k << 9) + (cg << 2));
            ulonglong2 w1 = *reinterpret_cast<const ulonglong2*>(WT + (k << 9) + 256 + (cg << 2));
            ull xd0 = pack2(xv.x), xd1 = pack2(xv.y), xd2 = pack2(xv.z), xd3 = pack2(xv.w);
            a2[0][0] = ffma2(xd0, w0.x, a2[0][0]); a2[0][1] = ffma2(xd0, w0.y, a2[0][1]);
            a2[0][2] = ffma2(xd0, w1.x, a2[0][2]); a2[0][3] = ffma2(xd0, w1.y, a2[0][3]);
            a2[1][0] = ffma2(xd1, w0.x, a2[1][0]); a2[1][1] = ffma2(xd1, w0.y, a2[1][1]);
            a2[1][2] = ffma2(xd1, w1.x, a2[1][2]); a2[1][3] = ffma2(xd1, w1.y, a2[1][3]);
            a2[2][0] = ffma2(xd2, w0.x, a2[2][0]); a2[2][1] = ffma2(xd2, w0.y, a2[2][1]);
            a2[2][2] = ffma2(xd2, w1.x, a2[2][2]); a2[2][3] = ffma2(xd2, w1.y, a2[2][3]);
            a2[3][0] = ffma2(xd3, w0.x, a2[3][0]); a2[3][1] = ffma2(xd3, w0.y, a2[3][1]);
            a2[3][2] = ffma2(xd3, w1.x, a2[3][2]); a2[3][3] = ffma2(xd3, w1.y, a2[3][3]);
        }
        float4 bb0 = *reinterpret_cast<const float4*>(bias + (cg << 2));
        float4 bb1 = *reinterpret_cast<const float4*>(bias + 256 + (cg << 2));
        #pragma unroll
        for (int r = 0; r < 4; ++r) {
            int n = rowbase + rg * 4 + r;
            int b = n >> 9;
            int t = n & 511;
            float* op = g_xg0 + ((size_t)t * B_ + b) * G_;
            float2 p0 = unpack2(a2[r][0]), p1v = unpack2(a2[r][1]);
            float2 p2 = unpack2(a2[r][2]), p3v = unpack2(a2[r][3]);
            float4 o0 = make_float4(p0.x + bb0.x, p0.y + bb0.y, p1v.x + bb0.z, p1v.y + bb0.w);
            float4 o1 = make_float4(p2.x + bb1.x, p2.y + bb1.y, p3v.x + bb1.z, p3v.y + bb1.w);
            *reinterpret_cast<float4*>(op + (cg << 2))       = o0;
            *reinterpret_cast<float4*>(op + 256 + (cg << 2)) = o1;
        }
    }
}

// ---------------------------------------------------------------------------
// Phase 2: persistent fused 2-layer scan, f32x2, rotated pipeline with
// split cluster barriers (arrive ... GEMM work ... wait) so both per-step
// cluster syncs are latency-hidden.
// ---------------------------------------------------------------------------
#define SC_THREADS 512
#define CL_N 4
#define BPC  8
#define HS   12
#define GS   9
#define W0T_OFF 0
#define W1T_OFF 16384
#define H_OFF   49152                 // 2 bufs * 256 k * 12
#define GT_OFF  55296                 // 128*9
#define B1_OFF  56448
#define SC_SMEM_FLOATS 56576          // 226304 B

__device__ __forceinline__ void gemm_half(const float* __restrict__ Wb,
                                          const float* __restrict__ hb,
                                          int kc, int rg, int bg, int k0,
                                          ull acc[16])
{
    #pragma unroll
    for (int ii = 0; ii < 8; ++ii) {
        int k = k0 + (ii << 4) + kc;
        const float* wr = Wb + (k << 7);
        int sw = k & 7;
        ulonglong2 wA = *reinterpret_cast<const ulonglong2*>(wr + ((((rg << 1)    ) ^ sw) << 2));
        ulonglong2 wB = *reinterpret_cast<const ulonglong2*>(wr + ((((rg << 1) | 1) ^ sw) << 2));
        float4 h = *reinterpret_cast<const float4*>(hb + k * HS + (bg << 2));
        ull h0 = pack2(h.x), h1 = pack2(h.y), h2 = pack2(h.z), h3 = pack2(h.w);
        acc[ 0] = ffma2(wA.x, h0, acc[ 0]); acc[ 1] = ffma2(wA.x, h1, acc[ 1]);
        acc[ 2] = ffma2(wA.x, h2, acc[ 2]); acc[ 3] = ffma2(wA.x, h3, acc[ 3]);
        acc[ 4] = ffma2(wA.y, h0, acc[ 4]); acc[ 5] = ffma2(wA.y, h1, acc[ 5]);
        acc[ 6] = ffma2(wA.y, h2, acc[ 6]); acc[ 7] = ffma2(wA.y, h3, acc[ 7]);
        acc[ 8] = ffma2(wB.x, h0, acc[ 8]); acc[ 9] = ffma2(wB.x, h1, acc[ 9]);
        acc[10] = ffma2(wB.x, h2, acc[10]); acc[11] = ffma2(wB.x, h3, acc[11]);
        acc[12] = ffma2(wB.y, h0, acc[12]); acc[13] = ffma2(wB.y, h1, acc[13]);
        acc[14] = ffma2(wB.y, h2, acc[14]); acc[15] = ffma2(wB.y, h3, acc[15]);
    }
}

__device__ __forceinline__ void fold_store(ull F[16], float* __restrict__ gates,
                                           int kc, int rg, int bg)
{
    {   // D=1: keep 8
        const bool hi = kc & 1;
        #pragma unroll
        for (int i = 0; i < 8; ++i) {
            ull give = hi ? F[i] : F[i + 8];
            ull keep = hi ? F[i + 8] : F[i];
            F[i] = add2(keep, __shfl_xor_sync(0xffffffffu, give, 1));
        }
    }
    {   // D=2: keep 4
        const bool hi = kc & 2;
        #pragma unroll
        for (int i = 0; i < 4; ++i) {
            ull give = hi ? F[i] : F[i + 4];
            ull keep = hi ? F[i + 4] : F[i];
            F[i] = add2(keep, __shfl_xor_sync(0xffffffffu, give, 2));
        }
    }
    {   // D=4: keep 2
        const bool hi = kc & 4;
        #pragma unroll
        for (int i = 0; i < 2; ++i) {
            ull give = hi ? F[i] : F[i + 2];
            ull keep = hi ? F[i + 2] : F[i];
            F[i] = add2(keep, __shfl_xor_sync(0xffffffffu, give, 4));
        }
    }
    {   // D=8: keep 1
        const bool hi = kc & 8;
        ull give = hi ? F[0] : F[1];
        ull keep = hi ? F[1] : F[0];
        F[0] = add2(keep, __shfl_xor_sync(0xffffffffu, give, 8));
    }
    const int rp = ((kc & 1) << 1) | ((kc >> 1) & 1);
    const int bb = (((kc >> 2) & 1) << 1) | ((kc >> 3) & 1);
    const int row0 = (rg << 3) + (rp << 1);
    float2 v = unpack2(F[0]);
    gates[row0 * GS + (bg << 2) + bb]       = v.x;
    gates[(row0 + 1) * GS + (bg << 2) + bb] = v.y;
}

__global__ void __launch_bounds__(SC_THREADS, 1) __cluster_dims__(CL_N, 1, 1)
scan_kernel(const float* __restrict__ w_hh0,
            const float* __restrict__ w_ih1,
            const float* __restrict__ w_hh1,
            const float* __restrict__ b_ih1,
            const float* __restrict__ b_hh1,
            const float* __restrict__ fc_w,
            const float* __restrict__ fc_b,
            float* __restrict__ out)
{
    extern __shared__ float s2[];
    float* W0T   = s2 + W0T_OFF;
    float* W1T   = s2 + W1T_OFF;
    float* Hbuf  = s2 + H_OFF;     // [buf][k 0..255][b], stride HS; k<128 h0, else h1
    float* gates = s2 + GT_OFF;    // [rl][b], stride GS
    float* bias1 = s2 + B1_OFF;

    const int tid = threadIdx.x;
    uint32_t rank;
    asm("mov.u32 %0, %%cluster_ctarank;" : "=r"(rank));
    const int irank = (int)rank;
    const int cbase = (blockIdx.x >> 2) * BPC;

    // ---- prologue ----
    for (int idx = tid; idx < 128 * 128; idx += SC_THREADS) {
        int rl = idx >> 7, k = idx & 127;
        int grow = ((rl >> 5) << 7) + irank * 32 + (rl & 31);
        int sa = (((rl >> 2) ^ (k & 7)) << 2) + (rl & 3);
        W0T[(k << 7) + sa]         = w_hh0[grow * H_ + k];
        W1T[(k << 7) + sa]         = w_ih1[grow * H_ + k];
        W1T[((128 + k) << 7) + sa] = w_hh1[grow * H_ + k];
    }
    for (int rl = tid; rl < 128; rl += SC_THREADS) {
        int grow = ((rl >> 5) << 7) + irank * 32 + (rl & 31);
        bias1[rl] = b_ih1[grow] + b_hh1[grow];
    }
    for (int i = tid; i < 2 * 256 * HS; i += SC_THREADS) Hbuf[i] = 0.0f;

    const uint32_t hloc = smem_u32(Hbuf);
    uint32_t hrem[4];
    #pragma unroll
    for (int r = 0; r < 4; ++r) hrem[r] = mapa_u32(hloc, (uint32_t)r);

    CLUSTER_SYNC();

    // GEMM mapping
    const int kc = tid & 15;
    const int tl = tid >> 4;
    const int bg = tl & 1;
    const int rg = tl >> 1;
    // elementwise mapping (tid < 256)
    const int eb  = tid >> 5;
    const int ej  = tid & 31;
    const int col = irank * 32 + ej;
    const float* xgbase = g_xg0 + (size_t)(cbase + eb) * G_ + col;

    float c0 = 0.0f, c1 = 0.0f;
    ull acc0[16];

    // pre-loop: GEMM0 for t=0 (h0_prev = zeros in buf 0) + xg prefetch
    #pragma unroll
    for (int i = 0; i < 16; ++i) acc0[i] = 0ull;
    gemm_half(W0T, Hbuf, kc, rg, bg, 0, acc0);
    float xg_i = 0.f, xg_f = 0.f, xg_g = 0.f, xg_o = 0.f;
    if (tid < 256) {
        xg_i = __ldg(xgbase);
        xg_f = __ldg(xgbase + 128);
        xg_g = __ldg(xgbase + 256);
        xg_o = __ldg(xgbase + 384);
    }

    for (int t = 0; t < T_; ++t) {
        const int p = t & 1;
        const int bufP = p ? 3072 : 0;        // holds h0_prev / h1_prev
        const int bufN = p ? 0 : 3072;        // receives h0_new / h1_new

        // ---- publish gates0, elementwise layer 0 ----
        fold_store(acc0, gates, kc, rg, bg);
        __syncthreads();
        if (tid < 256) {
            float gi = gates[ej * GS + eb]        + xg_i;
            float gf = gates[(32 + ej) * GS + eb] + xg_f;
            float gg = gates[(64 + ej) * GS + eb] + xg_g;
            float go = gates[(96 + ej) * GS + eb] + xg_o;
            float iv = sigf(gi), fv = sigf(gf), gv = tanh_f(gg), ov = sigf(go);
            c0 = fv * c0 + iv * gv;
            float h0 = ov * tanh_f(c0);
            uint32_t off = (uint32_t)((bufN + col * HS + eb) << 2);
            #pragma unroll
            for (int r = 0; r < 4; ++r) stc_f32(hrem[r] + off, h0);
        }
        CLUSTER_ARRIVE();                          // W0: h0_new release

        // ---- GEMM1b (h1_prev) overlaps barrier W0 ----
        ull acc1[16];
        #pragma unroll
        for (int i = 0; i < 16; ++i) acc1[i] = 0ull;
        gemm_half(W1T, Hbuf + bufP, kc, rg, bg, 128, acc1);   // ordered by W1 of t-1

        CLUSTER_WAIT();                            // h0_new visible cluster-wide

        // ---- GEMM1a (h0_new) + publish gates1 ----
        gemm_half(W1T, Hbuf + bufN, kc, rg, bg, 0, acc1);
        fold_store(acc1, gates, kc, rg, bg);       // WAR vs ew0 ordered by W0 wait
        __syncthreads();

        // ---- elementwise layer 1 ----
        if (tid < 256) {
            float gi = gates[ej * GS + eb]        + bias1[ej];
            float gf = gates[(32 + ej) * GS + eb] + bias1[32 + ej];
            float gg = gates[(64 + ej) * GS + eb] + bias1[64 + ej];
            float go = gates[(96 + ej) * GS + eb] + bias1[96 + ej];
            float iv = sigf(gi), fv = sigf(gf), gv = tanh_f(gg), ov = sigf(go);
            c1 = fv * c1 + iv * gv;
            float h1 = ov * tanh_f(c1);
            uint32_t off = (uint32_t)((bufN + (128 + col) * HS + eb) << 2);
            #pragma unroll
            for (int r = 0; r < 4; ++r) stc_f32(hrem[r] + off, h1);
        }
        CLUSTER_ARRIVE();                          // W1: h1_new release

        // ---- next step's GEMM0 + xg prefetch overlap barrier W1 ----
        if (t + 1 < T_) {
            #pragma unroll
            for (int i = 0; i < 16; ++i) acc0[i] = 0ull;
            gemm_half(W0T, Hbuf + bufN, kc, rg, bg, 0, acc0); // h0_new, visible since W0 wait
            if (tid < 256) {
                const float* xgp = xgbase + (size_t)(t + 1) * (B_ * G_);
                xg_i = __ldg(xgp);
                xg_f = __ldg(xgp + 128);
                xg_g = __ldg(xgp + 256);
                xg_o = __ldg(xgp + 384);
            }
        }
        CLUSTER_WAIT();                            // h1_new visible; full barrier
        // (gates WAR for next fold_store ordered by this wait)
    }

    // ---- epilogue: out[b] = fc_b + sum_c h1_last[b][c] * fc_w[c] ----
    // t=511: p=1, bufN=0 -> final h1 in buffer 0, rows 128..255 (visible after last W1 wait)
    if (irank == 0 && tid < 256) {
        const int b = tid >> 5;
        const int l = tid & 31;
        float ssum = 0.0f;
        #pragma unroll
        for (int cc = 0; cc < 4; ++cc) {
            int c = l * 4 + cc;
            ssum += Hbuf[(128 + c) * HS + b] * __ldg(fc_w + c);
        }
        #pragma unroll
        for (int d = 16; d > 0; d >>= 1)
            ssum += __shfl_xor_sync(0xffffffffu, ssum, d);
        if (l == 0) out[cbase + b] = ssum + __ldg(fc_b);
    }
    CLUSTER_SYNC();
}

// ---------------------------------------------------------------------------
extern "C" void kernel_launch(void* const* d_in, const int* in_sizes, int n_in,
                              void* d_out, int out_size)
{
    const float* x     = (const float*)d_in[0];
    const float* w_ih0 = (const float*)d_in[1];
    const float* w_hh0 = (const float*)d_in[2];
    const float* b_ih0 = (const float*)d_in[3];
    const float* b_hh0 = (const float*)d_in[4];
    const float* w_ih1 = (const float*)d_in[5];
    const float* w_hh1 = (const float*)d_in[6];
    const float* b_ih1 = (const float*)d_in[7];
    const float* b_hh1 = (const float*)d_in[8];
    const float* fc_w  = (const float*)d_in[9];
    const float* fc_b  = (const float*)d_in[10];
    float* out = (float*)d_out;

    const int p1_smem = P1_SMEM_FLOATS * 4;
    const int sc_smem = SC_SMEM_FLOATS * 4;
    cudaFuncSetAttribute(p1_kernel,   cudaFuncAttributeMaxDynamicSharedMemorySize, p1_smem);
    cudaFuncSetAttribute(scan_kernel, cudaFuncAttributeMaxDynamicSharedMemorySize, sc_smem);

    p1_kernel<<<(B_ * T_) / P1_ROWS, P1_THREADS, p1_smem>>>(x, w_ih0, b_ih0, b_hh0);
    scan_kernel<<<(B_ / BPC) * CL_N, SC_THREADS, sc_smem>>>(
        w_hh0, w_ih1, w_hh1, b_ih1, b_hh1, fc_w, fc_b, out);
}

// round 5
// speedup vs baseline: 1.2495x; 1.0017x over previous
#include <cuda_runtime.h>
#include <cstdint>

typedef unsigned long long ull;

#define B_   256
#define T_   512
#define IN_  64
#define H_   128
#define G_   512   // 4*H

// scratch for precomputed layer-0 input projections, layout [t][b][g]
__device__ float g_xg0[(size_t)T_ * B_ * G_];

// ---------------------------------------------------------------------------
// helpers
// ---------------------------------------------------------------------------
__device__ __forceinline__ uint32_t smem_u32(const void* p) {
    uint32_t a;
    asm("{ .reg .u64 t; cvta.to.shared.u64 t, %1; cvt.u32.u64 %0, t; }"
        : "=r"(a) : "l"(p));
    return a;
}
__device__ __forceinline__ uint32_t mapa_u32(uint32_t addr, uint32_t rank) {
    uint32_t r;
    asm("mapa.shared::cluster.u32 %0, %1, %2;" : "=r"(r) : "r"(addr), "r"(rank));
    return r;
}
__device__ __forceinline__ void stc_f32(uint32_t addr, float v) {
    asm volatile("st.shared::cluster.f32 [%0], %1;" :: "r"(addr), "f"(v));
}
#define CLUSTER_ARRIVE() asm volatile("barrier.cluster.arrive.aligned;" ::: "memory")
#define CLUSTER_WAIT()   asm volatile("barrier.cluster.wait.aligned;"   ::: "memory")
#define CLUSTER_SYNC() do { CLUSTER_ARRIVE(); CLUSTER_WAIT(); } while (0)

__device__ __forceinline__ float sigf(float x)  { return 1.0f / (1.0f + __expf(-x)); }
__device__ __forceinline__ float tanh_f(float x){ return 1.0f - 2.0f / (__expf(2.0f * x) + 1.0f); }

// ---- packed f32x2 (Blackwell) ----
__device__ __forceinline__ ull ffma2(ull a, ull b, ull c) {
    ull d;
    asm("fma.rn.f32x2 %0, %1, %2, %3;" : "=l"(d) : "l"(a), "l"(b), "l"(c));
    return d;
}
__device__ __forceinline__ ull add2(ull a, ull b) {
    ull c;
    asm("add.rn.f32x2 %0, %1, %2;" : "=l"(c) : "l"(a), "l"(b));
    return c;
}
__device__ __forceinline__ ull pack2(float x) {
    ull r;
    asm("mov.b64 %0, {%1, %1};" : "=l"(r) : "f"(x));
    return r;
}
__device__ __forceinline__ float2 unpack2(ull v) {
    float2 f;
    asm("mov.b64 {%0, %1}, %2;" : "=f"(f.x), "=f"(f.y) : "l"(v));
    return f;
}

// ---------------------------------------------------------------------------
// Phase 1: xg0[t][b][g] = (b_ih0+b_hh0)[g] + sum_i x[b][t][i] * w_ih0[g][i]
// ---------------------------------------------------------------------------
#define P1_ROWS    64
#define P1_THREADS 256
#define P1_XT_STRIDE 68
#define P1_WT_OFF   0
#define P1_XT_OFF   (64*512)
#define P1_B_OFF    (P1_XT_OFF + 64*P1_XT_STRIDE)
#define P1_SMEM_FLOATS (P1_B_OFF + 512)

__global__ void __launch_bounds__(P1_THREADS)
p1_kernel(const float* __restrict__ x,
          const float* __restrict__ w_ih0,
          const float* __restrict__ b_ih0,
          const float* __restrict__ b_hh0)
{
    extern __shared__ float s1[];
    float* WT   = s1 + P1_WT_OFF;
    float* xT   = s1 + P1_XT_OFF;
    float* bias = s1 + P1_B_OFF;

    const int tid     = threadIdx.x;
    const int rowbase = blockIdx.x * P1_ROWS;

    for (int idx = tid; idx < G_ * IN_; idx += P1_THREADS) {
        int g = idx >> 6, k = idx & 63;
        WT[k * 512 + g] = w_ih0[idx];
    }
    for (int g = tid; g < G_; g += P1_THREADS)
        bias[g] = b_ih0[g] + b_hh0[g];
    for (int idx = tid; idx < P1_ROWS * IN_ / 4; idx += P1_THREADS) {
        int row = idx >> 4, kq = idx & 15;
        float4 v = reinterpret_cast<const float4*>(x + (size_t)(rowbase + row) * IN_)[kq];
        int k = kq * 4;
        xT[(k + 0) * P1_XT_STRIDE + row] = v.x;
        xT[(k + 1) * P1_XT_STRIDE + row] = v.y;
        xT[(k + 2) * P1_XT_STRIDE + row] = v.z;
        xT[(k + 3) * P1_XT_STRIDE + row] = v.w;
    }
    __syncthreads();

    const int cg  = tid & 63;
    const int rgq = tid >> 6;

    for (int it = 0; it < 4; ++it) {
        const int rg = it * 4 + rgq;
        ull a2[4][4];
        #pragma unroll
        for (int r = 0; r < 4; ++r)
            #pragma unroll
            for (int c = 0; c < 4; ++c) a2[r][c] = 0ull;

        #pragma unroll 4
        for (int k = 0; k < IN_; ++k) {
            float4 xv = *reinterpret_cast<const float4*>(xT + k * P1_XT_STRIDE + (rg << 2));
            ulonglong2 w0 = *reinterpret_cast<const ulonglong2*>(WT + (k << 9) + (cg << 2));
            ulonglong2 w1 = *reinterpret_cast<const ulonglong2*>(WT + (k << 9) + 256 + (cg << 2));
            ull xd0 = pack2(xv.x), xd1 = pack2(xv.y), xd2 = pack2(xv.z), xd3 = pack2(xv.w);
            a2[0][0] = ffma2(xd0, w0.x, a2[0][0]); a2[0][1] = ffma2(xd0, w0.y, a2[0][1]);
            a2[0][2] = ffma2(xd0, w1.x, a2[0][2]); a2[0][3] = ffma2(xd0, w1.y, a2[0][3]);
            a2[1][0] = ffma2(xd1, w0.x, a2[1][0]); a2[1][1] = ffma2(xd1, w0.y, a2[1][1]);
            a2[1][2] = ffma2(xd1, w1.x, a2[1][2]); a2[1][3] = ffma2(xd1, w1.y, a2[1][3]);
            a2[2][0] = ffma2(xd2, w0.x, a2[2][0]); a2[2][1] = ffma2(xd2, w0.y, a2[2][1]);
            a2[2][2] = ffma2(xd2, w1.x, a2[2][2]); a2[2][3] = ffma2(xd2, w1.y, a2[2][3]);
            a2[3][0] = ffma2(xd3, w0.x, a2[3][0]); a2[3][1] = ffma2(xd3, w0.y, a2[3][1]);
            a2[3][2] = ffma2(xd3, w1.x, a2[3][2]); a2[3][3] = ffma2(xd3, w1.y, a2[3][3]);
        }
        float4 bb0 = *reinterpret_cast<const float4*>(bias + (cg << 2));
        float4 bb1 = *reinterpret_cast<const float4*>(bias + 256 + (cg << 2));
        #pragma unroll
        for (int r = 0; r < 4; ++r) {
            int n = rowbase + rg * 4 + r;
            int b = n >> 9;
            int t = n & 511;
            float* op = g_xg0 + ((size_t)t * B_ + b) * G_;
            float2 p0 = unpack2(a2[r][0]), p1v = unpack2(a2[r][1]);
            float2 p2 = unpack2(a2[r][2]), p3v = unpack2(a2[r][3]);
            float4 o0 = make_float4(p0.x + bb0.x, p0.y + bb0.y, p1v.x + bb0.z, p1v.y + bb0.w);
            float4 o1 = make_float4(p2.x + bb1.x, p2.y + bb1.y, p3v.x + bb1.z, p3v.y + bb1.w);
            *reinterpret_cast<float4*>(op + (cg << 2))       = o0;
            *reinterpret_cast<float4*>(op + 256 + (cg << 2)) = o1;
        }
    }
}

// ---------------------------------------------------------------------------
// Phase 2: persistent fused 2-layer scan, f32x2, rotated pipeline with
// split cluster barriers (arrive ... GEMM work ... wait) so both per-step
// cluster syncs are latency-hidden.
// ---------------------------------------------------------------------------
#define SC_THREADS 512
#define CL_N 4
#define BPC  8
#define HS   12
#define GS   9
#define W0T_OFF 0
#define W1T_OFF 16384
#define H_OFF   49152                 // 2 bufs * 256 k * 12
#define GT_OFF  55296                 // 128*9
#define B1_OFF  56448
#define SC_SMEM_FLOATS 56576          // 226304 B

__device__ __forceinline__ void gemm_half(const float* __restrict__ Wb,
                                          const float* __restrict__ hb,
                                          int kc, int rg, int bg, int k0,
                                          ull acc[16])
{
    #pragma unroll
    for (int ii = 0; ii < 8; ++ii) {
        int k = k0 + (ii << 4) + kc;
        const float* wr = Wb + (k << 7);
        int sw = k & 7;
        ulonglong2 wA = *reinterpret_cast<const ulonglong2*>(wr + ((((rg << 1)    ) ^ sw) << 2));
        ulonglong2 wB = *reinterpret_cast<const ulonglong2*>(wr + ((((rg << 1) | 1) ^ sw) << 2));
        float4 h = *reinterpret_cast<const float4*>(hb + k * HS + (bg << 2));
        ull h0 = pack2(h.x), h1 = pack2(h.y), h2 = pack2(h.z), h3 = pack2(h.w);
        acc[ 0] = ffma2(wA.x, h0, acc[ 0]); acc[ 1] = ffma2(wA.x, h1, acc[ 1]);
        acc[ 2] = ffma2(wA.x, h2, acc[ 2]); acc[ 3] = ffma2(wA.x, h3, acc[ 3]);
        acc[ 4] = ffma2(wA.y, h0, acc[ 4]); acc[ 5] = ffma2(wA.y, h1, acc[ 5]);
        acc[ 6] = ffma2(wA.y, h2, acc[ 6]); acc[ 7] = ffma2(wA.y, h3, acc[ 7]);
        acc[ 8] = ffma2(wB.x, h0, acc[ 8]); acc[ 9] = ffma2(wB.x, h1, acc[ 9]);
        acc[10] = ffma2(wB.x, h2, acc[10]); acc[11] = ffma2(wB.x, h3, acc[11]);
        acc[12] = ffma2(wB.y, h0, acc[12]); acc[13] = ffma2(wB.y, h1, acc[13]);
        acc[14] = ffma2(wB.y, h2, acc[14]); acc[15] = ffma2(wB.y, h3, acc[15]);
    }
}

__device__ __forceinline__ void fold_store(ull F[16], float* __restrict__ gates,
                                           int kc, int rg, int bg)
{
    {   // D=1: keep 8
        const bool hi = kc & 1;
        #pragma unroll
        for (int i = 0; i < 8; ++i) {
            ull give = hi ? F[i] : F[i + 8];
            ull keep = hi ? F[i + 8] : F[i];
            F[i] = add2(keep, __shfl_xor_sync(0xffffffffu, give, 1));
        }
    }
    {   // D=2: keep 4
        const bool hi = kc & 2;
        #pragma unroll
        for (int i = 0; i < 4; ++i) {
            ull give = hi ? F[i] : F[i + 4];
            ull keep = hi ? F[i + 4] : F[i];
            F[i] = add2(keep, __shfl_xor_sync(0xffffffffu, give, 2));
        }
    }
    {   // D=4: keep 2
        const bool hi = kc & 4;
        #pragma unroll
        for (int i = 0; i < 2; ++i) {
            ull give = hi ? F[i] : F[i + 2];
            ull keep = hi ? F[i + 2] : F[i];
            F[i] = add2(keep, __shfl_xor_sync(0xffffffffu, give, 4));
        }
    }
    {   // D=8: keep 1
        const bool hi = kc & 8;
        ull give = hi ? F[0] : F[1];
        ull keep = hi ? F[1] : F[0];
        F[0] = add2(keep, __shfl_xor_sync(0xffffffffu, give, 8));
    }
    const int rp = ((kc & 1) << 1) | ((kc >> 1) & 1);
    const int bb = (((kc >> 2) & 1) << 1) | ((kc >> 3) & 1);
    const int row0 = (rg << 3) + (rp << 1);
    float2 v = unpack2(F[0]);
    gates[row0 * GS + (bg << 2) + bb]       = v.x;
    gates[(row0 + 1) * GS + (bg << 2) + bb] = v.y;
}

__global__ void __launch_bounds__(SC_THREADS, 1) __cluster_dims__(CL_N, 1, 1)
scan_kernel(const float* __restrict__ w_hh0,
            const float* __restrict__ w_ih1,
            const float* __restrict__ w_hh1,
            const float* __restrict__ b_ih1,
            const float* __restrict__ b_hh1,
            const float* __restrict__ fc_w,
            const float* __restrict__ fc_b,
            float* __restrict__ out)
{
    extern __shared__ float s2[];
    float* W0T   = s2 + W0T_OFF;
    float* W1T   = s2 + W1T_OFF;
    float* Hbuf  = s2 + H_OFF;     // [buf][k 0..255][b], stride HS; k<128 h0, else h1
    float* gates = s2 + GT_OFF;    // [rl][b], stride GS
    float* bias1 = s2 + B1_OFF;

    const int tid = threadIdx.x;
    uint32_t rank;
    asm("mov.u32 %0, %%cluster_ctarank;" : "=r"(rank));
    const int irank = (int)rank;
    const int cbase = (blockIdx.x >> 2) * BPC;

    // ---- prologue ----
    for (int idx = tid; idx < 128 * 128; idx += SC_THREADS) {
        int rl = idx >> 7, k = idx & 127;
        int grow = ((rl >> 5) << 7) + irank * 32 + (rl & 31);
        int sa = (((rl >> 2) ^ (k & 7)) << 2) + (rl & 3);
        W0T[(k << 7) + sa]         = w_hh0[grow * H_ + k];
        W1T[(k << 7) + sa]         = w_ih1[grow * H_ + k];
        W1T[((128 + k) << 7) + sa] = w_hh1[grow * H_ + k];
    }
    for (int rl = tid; rl < 128; rl += SC_THREADS) {
        int grow = ((rl >> 5) << 7) + irank * 32 + (rl & 31);
        bias1[rl] = b_ih1[grow] + b_hh1[grow];
    }
    for (int i = tid; i < 2 * 256 * HS; i += SC_THREADS) Hbuf[i] = 0.0f;

    const uint32_t hloc = smem_u32(Hbuf);
    uint32_t hrem[4];
    #pragma unroll
    for (int r = 0; r < 4; ++r) hrem[r] = mapa_u32(hloc, (uint32_t)r);

    CLUSTER_SYNC();

    // GEMM mapping
    const int kc = tid & 15;
    const int tl = tid >> 4;
    const int bg = tl & 1;
    const int rg = tl >> 1;
    // elementwise mapping (tid < 256)
    const int eb  = tid >> 5;
    const int ej  = tid & 31;
    const int col = irank * 32 + ej;
    const float* xgbase = g_xg0 + (size_t)(cbase + eb) * G_ + col;

    float c0 = 0.0f, c1 = 0.0f;
    ull acc0[16];

    // pre-loop: GEMM0 for t=0 (h0_prev = zeros in buf 0) + xg prefetch
    #pragma unroll
    for (int i = 0; i < 16; ++i) acc0[i] = 0ull;
    gemm_half(W0T, Hbuf, kc, rg, bg, 0, acc0);
    float xg_i = 0.f, xg_f = 0.f, xg_g = 0.f, xg_o = 0.f;
    if (tid < 256) {
        xg_i = __ldg(xgbase);
        xg_f = __ldg(xgbase + 128);
        xg_g = __ldg(xgbase + 256);
        xg_o = __ldg(xgbase + 384);
    }

    for (int t = 0; t < T_; ++t) {
        const int p = t & 1;
        const int bufP = p ? 3072 : 0;        // holds h0_prev / h1_prev
        const int bufN = p ? 0 : 3072;        // receives h0_new / h1_new

        // ---- publish gates0, elementwise layer 0 ----
        fold_store(acc0, gates, kc, rg, bg);
        __syncthreads();
        if (tid < 256) {
            float gi = gates[ej * GS + eb]        + xg_i;
            float gf = gates[(32 + ej) * GS + eb] + xg_f;
            float gg = gates[(64 + ej) * GS + eb] + xg_g;
            float go = gates[(96 + ej) * GS + eb] + xg_o;
            float iv = sigf(gi), fv = sigf(gf), gv = tanh_f(gg), ov = sigf(go);
            c0 = fv * c0 + iv * gv;
            float h0 = ov * tanh_f(c0);
            uint32_t off = (uint32_t)((bufN + col * HS + eb) << 2);
            #pragma unroll
            for (int r = 0; r < 4; ++r) stc_f32(hrem[r] + off, h0);
        }
        CLUSTER_ARRIVE();                          // W0: h0_new release

        // ---- GEMM1b (h1_prev) overlaps barrier W0 ----
        ull acc1[16];
        #pragma unroll
        for (int i = 0; i < 16; ++i) acc1[i] = 0ull;
        gemm_half(W1T, Hbuf + bufP, kc, rg, bg, 128, acc1);   // ordered by W1 of t-1

        CLUSTER_WAIT();                            // h0_new visible cluster-wide

        // ---- GEMM1a (h0_new) + publish gates1 ----
        gemm_half(W1T, Hbuf + bufN, kc, rg, bg, 0, acc1);
        fold_store(acc1, gates, kc, rg, bg);       // WAR vs ew0 ordered by W0 wait
        __syncthreads();

        // ---- elementwise layer 1 ----
        if (tid < 256) {
            float gi = gates[ej * GS + eb]        + bias1[ej];
            float gf = gates[(32 + ej) * GS + eb] + bias1[32 + ej];
            float gg = gates[(64 + ej) * GS + eb] + bias1[64 + ej];
            float go = gates[(96 + ej) * GS + eb] + bias1[96 + ej];
            float iv = sigf(gi), fv = sigf(gf), gv = tanh_f(gg), ov = sigf(go);
            c1 = fv * c1 + iv * gv;
            float h1 = ov * tanh_f(c1);
            uint32_t off = (uint32_t)((bufN + (128 + col) * HS + eb) << 2);
            #pragma unroll
            for (int r = 0; r < 4; ++r) stc_f32(hrem[r] + off, h1);
        }
        CLUSTER_ARRIVE();                          // W1: h1_new release

        // ---- next step's GEMM0 + xg prefetch overlap barrier W1 ----
        if (t + 1 < T_) {
            #pragma unroll
            for (int i = 0; i < 16; ++i) acc0[i] = 0ull;
            gemm_half(W0T, Hbuf + bufN, kc, rg, bg, 0, acc0); // h0_new, visible since W0 wait
            if (tid < 256) {
                const float* xgp = xgbase + (size_t)(t + 1) * (B_ * G_);
                xg_i = __ldg(xgp);
                xg_f = __ldg(xgp + 128);
                xg_g = __ldg(xgp + 256);
                xg_o = __ldg(xgp + 384);
            }
        }
        CLUSTER_WAIT();                            // h1_new visible; full barrier
        // (gates WAR for next fold_store ordered by this wait)
    }

    // ---- epilogue: out[b] = fc_b + sum_c h1_last[b][c] * fc_w[c] ----
    // t=511: p=1, bufN=0 -> final h1 in buffer 0, rows 128..255 (visible after last W1 wait)
    if (irank == 0 && tid < 256) {
        const int b = tid >> 5;
        const int l = tid & 31;
        float ssum = 0.0f;
        #pragma unroll
        for (int cc = 0; cc < 4; ++cc) {
            int c = l * 4 + cc;
            ssum += Hbuf[(128 + c) * HS + b] * __ldg(fc_w + c);
        }
        #pragma unroll
        for (int d = 16; d > 0; d >>= 1)
            ssum += __shfl_xor_sync(0xffffffffu, ssum, d);
        if (l == 0) out[cbase + b] = ssum + __ldg(fc_b);
    }
    CLUSTER_SYNC();
}

// ---------------------------------------------------------------------------
extern "C" void kernel_launch(void* const* d_in, const int* in_sizes, int n_in,
                              void* d_out, int out_size)
{
    const float* x     = (const float*)d_in[0];
    const float* w_ih0 = (const float*)d_in[1];
    const float* w_hh0 = (const float*)d_in[2];
    const float* b_ih0 = (const float*)d_in[3];
    const float* b_hh0 = (const float*)d_in[4];
    const float* w_ih1 = (const float*)d_in[5];
    const float* w_hh1 = (const float*)d_in[6];
    const float* b_ih1 = (const float*)d_in[7];
    const float* b_hh1 = (const float*)d_in[8];
    const float* fc_w  = (const float*)d_in[9];
    const float* fc_b  = (const float*)d_in[10];
    float* out = (float*)d_out;

    const int p1_smem = P1_SMEM_FLOATS * 4;
    const int sc_smem = SC_SMEM_FLOATS * 4;
    cudaFuncSetAttribute(p1_kernel,   cudaFuncAttributeMaxDynamicSharedMemorySize, p1_smem);
    cudaFuncSetAttribute(scan_kernel, cudaFuncAttributeMaxDynamicSharedMemorySize, sc_smem);

    p1_kernel<<<(B_ * T_) / P1_ROWS, P1_THREADS, p1_smem>>>(x, w_ih0, b_ih0, b_hh0);
    scan_kernel<<<(B_ / BPC) * CL_N, SC_THREADS, sc_smem>>>(
        w_hh0, w_ih1, w_hh1, b_ih1, b_hh1, fc_w, fc_b, out);
}